// round 2
// baseline (speedup 1.0000x reference)
#include <cuda_runtime.h>

// Problem dims
#define Bb   8
#define Ss   1024
#define Dd   1024
#define Hh   16
#define DKk  64
#define DFFf 4096
#define MR   (Bb * Ss)   // 8192 rows

// ---------------- scratch (device globals; no allocations allowed) -------------
__device__ float g_xn  [(size_t)MR * Dd];          // 32 MB (LN out, reused)
__device__ float g_q   [(size_t)MR * Dd];          // 32 MB
__device__ float g_k   [(size_t)MR * Dd];          // 32 MB
__device__ float g_v   [(size_t)MR * Dd];          // 32 MB
__device__ float g_sc  [(size_t)Bb * Hh * Ss * Ss];// 512 MB attention scores
__device__ float g_attn[(size_t)MR * Dd];          // 32 MB
__device__ float g_x1  [(size_t)MR * Dd];          // 32 MB
__device__ float g_ff1 [(size_t)MR * DFFf];        // 128 MB

// ---------------- LayerNorm (ddof=1, scalar gamma/beta) ------------------------
__global__ void __launch_bounds__(256) ln_kernel(
    const float* __restrict__ x, float* __restrict__ out,
    const float* __restrict__ gamma, const float* __restrict__ beta)
{
    const int row = blockIdx.x;
    const float* xr = x + (size_t)row * Dd;
    float s = 0.f, sq = 0.f;
    for (int i = threadIdx.x; i < Dd; i += 256) {
        float v = xr[i]; s += v; sq += v * v;
    }
    #pragma unroll
    for (int o = 16; o > 0; o >>= 1) {
        s  += __shfl_xor_sync(0xffffffffu, s, o);
        sq += __shfl_xor_sync(0xffffffffu, sq, o);
    }
    __shared__ float rs[8], rq[8];
    __shared__ float bmu, brstd;
    const int w = threadIdx.x >> 5, l = threadIdx.x & 31;
    if (l == 0) { rs[w] = s; rq[w] = sq; }
    __syncthreads();
    if (threadIdx.x == 0) {
        float ts = 0.f, tq = 0.f;
        #pragma unroll
        for (int i = 0; i < 8; i++) { ts += rs[i]; tq += rq[i]; }
        float mu  = ts / (float)Dd;
        float var = (tq - (float)Dd * mu * mu) / (float)(Dd - 1);
        bmu = mu; brstd = rsqrtf(var + 1e-5f);
    }
    __syncthreads();
    const float g = gamma[0], be = beta[0];
    const float mu = bmu, rstd = brstd;
    float* orow = out + (size_t)row * Dd;
    for (int i = threadIdx.x; i < Dd; i += 256)
        orow[i] = g * (xr[i] - mu) * rstd + be;
}

// ---------------- Generic NT SGEMM: C = A[M,K] * W[N,K]^T (+bias, +res, relu) ---
// 128x128 tile, BK=8, 256 threads, 8x8 microtile. M,N,K multiples of 128/8.
template<int RELU, int RES>
__global__ void __launch_bounds__(256) gemm_nt(
    const float* __restrict__ A, const float* __restrict__ W,
    const float* __restrict__ bias, const float* __restrict__ res,
    float* __restrict__ C, int K, int N)
{
    __shared__ float As[8][128];
    __shared__ float Bs[8][128];
    const int tid = threadIdx.x;
    const int tx = tid & 15, ty = tid >> 4;
    const int rowBase = blockIdx.y * 128;
    const int colBase = blockIdx.x * 128;

    const int lRow = tid >> 1;            // 0..127
    const int lCol = (tid & 1) * 4;       // 0 or 4
    const float* Ap = A + (size_t)(rowBase + lRow) * K + lCol;
    const float* Wp = W + (size_t)(colBase + lRow) * K + lCol;

    float acc[8][8];
    #pragma unroll
    for (int i = 0; i < 8; i++)
        #pragma unroll
        for (int j = 0; j < 8; j++) acc[i][j] = 0.f;

    for (int k0 = 0; k0 < K; k0 += 8) {
        float4 av = *(const float4*)(Ap + k0);
        float4 wv = *(const float4*)(Wp + k0);
        As[lCol + 0][lRow] = av.x; As[lCol + 1][lRow] = av.y;
        As[lCol + 2][lRow] = av.z; As[lCol + 3][lRow] = av.w;
        Bs[lCol + 0][lRow] = wv.x; Bs[lCol + 1][lRow] = wv.y;
        Bs[lCol + 2][lRow] = wv.z; Bs[lCol + 3][lRow] = wv.w;
        __syncthreads();
        #pragma unroll
        for (int k = 0; k < 8; k++) {
            float a[8], b[8];
            *(float4*)(a)     = *(const float4*)&As[k][ty * 8];
            *(float4*)(a + 4) = *(const float4*)&As[k][ty * 8 + 4];
            *(float4*)(b)     = *(const float4*)&Bs[k][tx * 8];
            *(float4*)(b + 4) = *(const float4*)&Bs[k][tx * 8 + 4];
            #pragma unroll
            for (int i = 0; i < 8; i++)
                #pragma unroll
                for (int j = 0; j < 8; j++)
                    acc[i][j] = fmaf(a[i], b[j], acc[i][j]);
        }
        __syncthreads();
    }

    #pragma unroll
    for (int i = 0; i < 8; i++) {
        const int r = rowBase + ty * 8 + i;
        #pragma unroll
        for (int j = 0; j < 8; j += 4) {
            const int c = colBase + tx * 8 + j;
            float4 bv = *(const float4*)&bias[c];
            float4 o;
            o.x = acc[i][j + 0] + bv.x;
            o.y = acc[i][j + 1] + bv.y;
            o.z = acc[i][j + 2] + bv.z;
            o.w = acc[i][j + 3] + bv.w;
            if (RELU) {
                o.x = fmaxf(o.x, 0.f); o.y = fmaxf(o.y, 0.f);
                o.z = fmaxf(o.z, 0.f); o.w = fmaxf(o.w, 0.f);
            }
            if (RES) {
                float4 rv = *(const float4*)&res[(size_t)r * N + c];
                o.x += rv.x; o.y += rv.y; o.z += rv.z; o.w += rv.w;
            }
            *(float4*)&C[(size_t)r * N + c] = o;
        }
    }
}

// ---------------- Attention scores: S[b,h] = Q[b,h] * K[b,h]^T / 8 -------------
// 64x64 tile per block, K-dim = 64 (whole head) in one shot.
__global__ void __launch_bounds__(256) scores_kernel(
    const float* __restrict__ Q, const float* __restrict__ Kg,
    float* __restrict__ Sc)
{
    const int bh = blockIdx.z;
    const int b = bh >> 4, h = bh & 15;
    const int q0 = blockIdx.y * 64, k0 = blockIdx.x * 64;
    __shared__ float Qs[64][68];
    __shared__ float Ks[64][68];
    const int tid = threadIdx.x;
    const size_t headOff = ((size_t)b * Ss) * Dd + (size_t)h * DKk;

    #pragma unroll
    for (int r = 0; r < 4; r++) {
        int f4  = tid + 256 * r;       // 0..1023
        int row = f4 >> 4;             // 0..63
        int c4  = (f4 & 15) << 2;      // 0..60
        float4 qv = *(const float4*)(Q  + headOff + (size_t)(q0 + row) * Dd + c4);
        float4 kv = *(const float4*)(Kg + headOff + (size_t)(k0 + row) * Dd + c4);
        Qs[c4 + 0][row] = qv.x; Qs[c4 + 1][row] = qv.y;
        Qs[c4 + 2][row] = qv.z; Qs[c4 + 3][row] = qv.w;
        Ks[c4 + 0][row] = kv.x; Ks[c4 + 1][row] = kv.y;
        Ks[c4 + 2][row] = kv.z; Ks[c4 + 3][row] = kv.w;
    }
    __syncthreads();

    const int tx = tid & 15, ty = tid >> 4;
    float acc[4][4];
    #pragma unroll
    for (int i = 0; i < 4; i++)
        #pragma unroll
        for (int j = 0; j < 4; j++) acc[i][j] = 0.f;

    #pragma unroll 8
    for (int kk = 0; kk < 64; kk++) {
        float a[4], bv[4];
        *(float4*)a  = *(const float4*)&Qs[kk][ty * 4];
        *(float4*)bv = *(const float4*)&Ks[kk][tx * 4];
        #pragma unroll
        for (int i = 0; i < 4; i++)
            #pragma unroll
            for (int j = 0; j < 4; j++)
                acc[i][j] = fmaf(a[i], bv[j], acc[i][j]);
    }

    #pragma unroll
    for (int i = 0; i < 4; i++) {
        float* dst = Sc + ((size_t)bh * Ss + q0 + ty * 4 + i) * Ss + k0 + tx * 4;
        float4 o = { acc[i][0] * 0.125f, acc[i][1] * 0.125f,
                     acc[i][2] * 0.125f, acc[i][3] * 0.125f };
        *(float4*)dst = o;
    }
}

// ---------------- Row softmax over 1024 (in place) -----------------------------
__global__ void __launch_bounds__(256) softmax_kernel(float* __restrict__ Sc)
{
    float* p = Sc + (size_t)blockIdx.x * Ss;
    const int t = threadIdx.x;
    float v[4];
    float mx = -3.4e38f;
    #pragma unroll
    for (int i = 0; i < 4; i++) { v[i] = p[t + 256 * i]; mx = fmaxf(mx, v[i]); }
    __shared__ float rmax[8], rsum[8];
    __shared__ float bmax, binv;
    #pragma unroll
    for (int o = 16; o > 0; o >>= 1) mx = fmaxf(mx, __shfl_xor_sync(0xffffffffu, mx, o));
    if ((t & 31) == 0) rmax[t >> 5] = mx;
    __syncthreads();
    if (t == 0) {
        float m = rmax[0];
        #pragma unroll
        for (int i = 1; i < 8; i++) m = fmaxf(m, rmax[i]);
        bmax = m;
    }
    __syncthreads();
    mx = bmax;
    float sum = 0.f;
    #pragma unroll
    for (int i = 0; i < 4; i++) { v[i] = __expf(v[i] - mx); sum += v[i]; }
    #pragma unroll
    for (int o = 16; o > 0; o >>= 1) sum += __shfl_xor_sync(0xffffffffu, sum, o);
    if ((t & 31) == 0) rsum[t >> 5] = sum;
    __syncthreads();
    if (t == 0) {
        float s2 = 0.f;
        #pragma unroll
        for (int i = 0; i < 8; i++) s2 += rsum[i];
        binv = 1.f / s2;
    }
    __syncthreads();
    const float inv = binv;
    #pragma unroll
    for (int i = 0; i < 4; i++) p[t + 256 * i] = v[i] * inv;
}

// ---------------- PV: O[b,h] = P[b,h](1024x1024) @ V[b,h](1024x64) --------------
// 128 q-rows per block, all 64 cols, BK=16; 256 threads, 8x4 microtile.
__global__ void __launch_bounds__(256) pv_kernel(
    const float* __restrict__ P, const float* __restrict__ V,
    float* __restrict__ O)
{
    const int bh = blockIdx.y;
    const int b = bh >> 4, h = bh & 15;
    const int q0 = blockIdx.x * 128;
    const float* Pb = P + (size_t)bh * Ss * Ss;
    const size_t vOff = ((size_t)b * Ss) * Dd + (size_t)h * DKk;
    __shared__ float Ps[16][128];
    __shared__ float Vs[16][64];
    const int tid = threadIdx.x;
    const int tx = tid & 15, ty = tid >> 4;

    float acc[8][4];
    #pragma unroll
    for (int i = 0; i < 8; i++)
        #pragma unroll
        for (int j = 0; j < 4; j++) acc[i][j] = 0.f;

    for (int kb = 0; kb < Ss; kb += 16) {
        #pragma unroll
        for (int r = 0; r < 2; r++) {
            int f4  = tid + 256 * r;     // 0..511
            int row = f4 >> 2;           // 0..127
            int c4  = (f4 & 3) << 2;     // 0..12
            float4 pv = *(const float4*)(Pb + (size_t)(q0 + row) * Ss + kb + c4);
            Ps[c4 + 0][row] = pv.x; Ps[c4 + 1][row] = pv.y;
            Ps[c4 + 2][row] = pv.z; Ps[c4 + 3][row] = pv.w;
        }
        {
            int row = tid >> 4;          // 0..15
            int c4  = (tid & 15) << 2;   // 0..60
            *(float4*)&Vs[row][c4] =
                *(const float4*)(V + vOff + (size_t)(kb + row) * Dd + c4);
        }
        __syncthreads();
        #pragma unroll
        for (int kk = 0; kk < 16; kk++) {
            float a[8], bv[4];
            *(float4*)(a)     = *(const float4*)&Ps[kk][ty * 8];
            *(float4*)(a + 4) = *(const float4*)&Ps[kk][ty * 8 + 4];
            *(float4*)(bv)    = *(const float4*)&Vs[kk][tx * 4];
            #pragma unroll
            for (int i = 0; i < 8; i++)
                #pragma unroll
                for (int j = 0; j < 4; j++)
                    acc[i][j] = fmaf(a[i], bv[j], acc[i][j]);
        }
        __syncthreads();
    }
    #pragma unroll
    for (int i = 0; i < 8; i++) {
        float4 o = { acc[i][0], acc[i][1], acc[i][2], acc[i][3] };
        *(float4*)&O[((size_t)b * Ss + q0 + ty * 8 + i) * Dd + (size_t)h * DKk + tx * 4] = o;
    }
}

// ---------------- launch --------------------------------------------------------
extern "C" void kernel_launch(void* const* d_in, const int* in_sizes, int n_in,
                              void* d_out, int out_size)
{
    const float* x   = (const float*)d_in[0];
    // d_in[1] = src_mask (no-op in reference)
    const float* wq  = (const float*)d_in[2];
    const float* bq  = (const float*)d_in[3];
    const float* wk  = (const float*)d_in[4];
    const float* bk  = (const float*)d_in[5];
    const float* wv  = (const float*)d_in[6];
    const float* bv  = (const float*)d_in[7];
    const float* wo  = (const float*)d_in[8];
    const float* bo  = (const float*)d_in[9];
    const float* w1  = (const float*)d_in[10];
    const float* b1  = (const float*)d_in[11];
    const float* w2  = (const float*)d_in[12];
    const float* b2  = (const float*)d_in[13];
    const float* g1  = (const float*)d_in[14];
    const float* be1 = (const float*)d_in[15];
    const float* g2  = (const float*)d_in[16];
    const float* be2 = (const float*)d_in[17];
    float* out = (float*)d_out;

    float *xn, *q, *k, *v, *sc, *attn, *x1, *ff1;
    cudaGetSymbolAddress((void**)&xn,   g_xn);
    cudaGetSymbolAddress((void**)&q,    g_q);
    cudaGetSymbolAddress((void**)&k,    g_k);
    cudaGetSymbolAddress((void**)&v,    g_v);
    cudaGetSymbolAddress((void**)&sc,   g_sc);
    cudaGetSymbolAddress((void**)&attn, g_attn);
    cudaGetSymbolAddress((void**)&x1,   g_x1);
    cudaGetSymbolAddress((void**)&ff1,  g_ff1);

    // 1. LN1
    ln_kernel<<<MR, 256>>>(x, xn, g1, be1);
    // 2. Q,K,V projections
    gemm_nt<0,0><<<dim3(Dd/128, MR/128), 256>>>(xn, wq, bq, nullptr, q,  Dd, Dd);
    gemm_nt<0,0><<<dim3(Dd/128, MR/128), 256>>>(xn, wk, bk, nullptr, k,  Dd, Dd);
    gemm_nt<0,0><<<dim3(Dd/128, MR/128), 256>>>(xn, wv, bv, nullptr, v,  Dd, Dd);
    // 3. scores + softmax + PV
    scores_kernel<<<dim3(Ss/64, Ss/64, Bb*Hh), 256>>>(q, k, sc);
    softmax_kernel<<<Bb*Hh*Ss, 256>>>(sc);
    pv_kernel<<<dim3(Ss/128, Bb*Hh), 256>>>(sc, v, attn);
    // 4. output projection + residual
    gemm_nt<0,1><<<dim3(Dd/128, MR/128), 256>>>(attn, wo, bo, x, x1, Dd, Dd);
    // 5. LN2
    ln_kernel<<<MR, 256>>>(x1, xn, g2, be2);
    // 6. FFN
    gemm_nt<1,0><<<dim3(DFFf/128, MR/128), 256>>>(xn,  w1, b1, nullptr, ff1, Dd,   DFFf);
    gemm_nt<0,1><<<dim3(Dd/128,   MR/128), 256>>>(ff1, w2, b2, x1,      out, DFFf, Dd);
}

// round 5
// speedup vs baseline: 2.2966x; 2.2966x over previous
#include <cuda_runtime.h>
#include <cuda_bf16.h>
#include <cstdint>

// Problem dims
#define Bb   8
#define Ss   1024
#define Dd   1024
#define Hh   16
#define DKk  64
#define DFFf 4096
#define MR   (Bb * Ss)   // 8192 rows

// ---------------- scratch (device globals; no allocations allowed) -------------
__device__ float g_q   [(size_t)MR * Dd];
__device__ float g_k   [(size_t)MR * Dd];
__device__ float g_v   [(size_t)MR * Dd];
__device__ float g_sc  [(size_t)Bb * Hh * Ss * Ss];   // 512 MB scores
__device__ float g_x1  [(size_t)MR * Dd];

__device__ __nv_bfloat16 g_xn_hi[(size_t)MR * Dd];
__device__ __nv_bfloat16 g_xn_lo[(size_t)MR * Dd];
__device__ __nv_bfloat16 g_at_hi[(size_t)MR * Dd];
__device__ __nv_bfloat16 g_at_lo[(size_t)MR * Dd];
__device__ __nv_bfloat16 g_f1_hi[(size_t)MR * DFFf];
__device__ __nv_bfloat16 g_f1_lo[(size_t)MR * DFFf];
__device__ __nv_bfloat16 g_wq_hi[(size_t)Dd * Dd];
__device__ __nv_bfloat16 g_wq_lo[(size_t)Dd * Dd];
__device__ __nv_bfloat16 g_wk_hi[(size_t)Dd * Dd];
__device__ __nv_bfloat16 g_wk_lo[(size_t)Dd * Dd];
__device__ __nv_bfloat16 g_wv_hi[(size_t)Dd * Dd];
__device__ __nv_bfloat16 g_wv_lo[(size_t)Dd * Dd];
__device__ __nv_bfloat16 g_wo_hi[(size_t)Dd * Dd];
__device__ __nv_bfloat16 g_wo_lo[(size_t)Dd * Dd];
__device__ __nv_bfloat16 g_w1_hi[(size_t)DFFf * Dd];
__device__ __nv_bfloat16 g_w1_lo[(size_t)DFFf * Dd];
__device__ __nv_bfloat16 g_w2_hi[(size_t)Dd * DFFf];
__device__ __nv_bfloat16 g_w2_lo[(size_t)Dd * DFFf];

// ---------------- helpers -------------------------------------------------------
__device__ __forceinline__ uint32_t smem_to_u32(const void* p) {
    uint32_t a;
    asm("{ .reg .u64 t; cvta.to.shared.u64 t, %1; cvt.u32.u64 %0, t; }" : "=r"(a) : "l"(p));
    return a;
}
#define SWZ(off) ((off) ^ (((off) >> 3) & 0x70))

#define CP_ASYNC16(dst, src) \
    asm volatile("cp.async.cg.shared.global [%0], [%1], 16;" :: "r"(dst), "l"(src))
#define CP_COMMIT()  asm volatile("cp.async.commit_group;" ::: "memory")
#define CP_WAIT0()   asm volatile("cp.async.wait_group 0;" ::: "memory")
#define CP_WAIT1()   asm volatile("cp.async.wait_group 1;" ::: "memory")

__device__ __forceinline__ void ldsm4(uint32_t& r0, uint32_t& r1, uint32_t& r2, uint32_t& r3,
                                      uint32_t addr) {
    asm volatile("ldmatrix.sync.aligned.m8n8.x4.shared.b16 {%0,%1,%2,%3}, [%4];"
        : "=r"(r0), "=r"(r1), "=r"(r2), "=r"(r3) : "r"(addr));
}
__device__ __forceinline__ void mma_bf16(float* c, const uint32_t* a, const uint32_t* b) {
    asm volatile(
        "mma.sync.aligned.m16n8k16.row.col.f32.bf16.bf16.f32 "
        "{%0,%1,%2,%3}, {%4,%5,%6,%7}, {%8,%9}, {%0,%1,%2,%3};"
        : "+f"(c[0]), "+f"(c[1]), "+f"(c[2]), "+f"(c[3])
        : "r"(a[0]), "r"(a[1]), "r"(a[2]), "r"(a[3]), "r"(b[0]), "r"(b[1]));
}

__device__ __forceinline__ void split_hilo(float x, __nv_bfloat16& h, __nv_bfloat16& l) {
    h = __float2bfloat16(x);
    l = __float2bfloat16(x - __bfloat162float(h));
}

// ---------------- LayerNorm -> bf16 hi/lo output -------------------------------
__global__ void __launch_bounds__(256) ln_kernel(
    const float* __restrict__ x,
    __nv_bfloat16* __restrict__ ohi, __nv_bfloat16* __restrict__ olo,
    const float* __restrict__ gamma, const float* __restrict__ beta)
{
    const int row = blockIdx.x;
    const float* xr = x + (size_t)row * Dd;
    float s = 0.f, sq = 0.f;
    for (int i = threadIdx.x; i < Dd; i += 256) {
        float v = xr[i]; s += v; sq += v * v;
    }
    #pragma unroll
    for (int o = 16; o > 0; o >>= 1) {
        s  += __shfl_xor_sync(0xffffffffu, s, o);
        sq += __shfl_xor_sync(0xffffffffu, sq, o);
    }
    __shared__ float rs[8], rq[8];
    __shared__ float bmu, brstd;
    const int w = threadIdx.x >> 5, l = threadIdx.x & 31;
    if (l == 0) { rs[w] = s; rq[w] = sq; }
    __syncthreads();
    if (threadIdx.x == 0) {
        float ts = 0.f, tq = 0.f;
        #pragma unroll
        for (int i = 0; i < 8; i++) { ts += rs[i]; tq += rq[i]; }
        float mu  = ts / (float)Dd;
        float var = (tq - (float)Dd * mu * mu) / (float)(Dd - 1);
        bmu = mu; brstd = rsqrtf(var + 1e-5f);
    }
    __syncthreads();
    const float g = gamma[0], be = beta[0];
    const float mu = bmu, rstd = brstd;
    for (int i = threadIdx.x; i < Dd; i += 256) {
        float v = g * (xr[i] - mu) * rstd + be;
        __nv_bfloat16 h, lo2;
        split_hilo(v, h, lo2);
        ohi[(size_t)row * Dd + i] = h;
        olo[(size_t)row * Dd + i] = lo2;
    }
}

// ---------------- fp32 -> bf16 hi/lo conversion (weights) ----------------------
__global__ void __launch_bounds__(256) conv_hilo(
    const float* __restrict__ x,
    __nv_bfloat16* __restrict__ hi, __nv_bfloat16* __restrict__ lo, int n4)
{
    int i = blockIdx.x * 256 + threadIdx.x;
    if (i >= n4) return;
    float4 v = ((const float4*)x)[i];
    __nv_bfloat16 h0, l0, h1, l1, h2, l2, h3, l3;
    split_hilo(v.x, h0, l0); split_hilo(v.y, h1, l1);
    split_hilo(v.z, h2, l2); split_hilo(v.w, h3, l3);
    uint32_t hA = (uint32_t)__bfloat16_as_ushort(h0) | ((uint32_t)__bfloat16_as_ushort(h1) << 16);
    uint32_t hB = (uint32_t)__bfloat16_as_ushort(h2) | ((uint32_t)__bfloat16_as_ushort(h3) << 16);
    uint32_t lA = (uint32_t)__bfloat16_as_ushort(l0) | ((uint32_t)__bfloat16_as_ushort(l1) << 16);
    uint32_t lB = (uint32_t)__bfloat16_as_ushort(l2) | ((uint32_t)__bfloat16_as_ushort(l3) << 16);
    ((uint2*)hi)[i] = make_uint2(hA, hB);
    ((uint2*)lo)[i] = make_uint2(lA, lB);
}

// ---------------- split-bf16 mma.sync GEMM: C = A * W^T ------------------------
// MODE 0: out fp32 = acc + bias
// MODE 1: out fp32 = acc + bias + res
// MODE 2: relu(acc + bias) -> bf16 hi/lo
// CTA tile 128x128, BK=64. 512 threads = 16 warps (4x4), warp tile 32x32.
#define T_AHI 0
#define T_ALO 16384
#define T_WHI 32768
#define T_WLO 49152
#define STAGE 65536
#define GEMM_SMEM_DYN 131072

template<int MODE>
__global__ void __launch_bounds__(512) gemm_mma(
    const __nv_bfloat16* __restrict__ Ahi, const __nv_bfloat16* __restrict__ Alo,
    const __nv_bfloat16* __restrict__ Whi, const __nv_bfloat16* __restrict__ Wlo,
    const float* __restrict__ bias, const float* __restrict__ res,
    float* __restrict__ outF,
    __nv_bfloat16* __restrict__ outHi, __nv_bfloat16* __restrict__ outLo,
    int K, int N)
{
    extern __shared__ char smem[];
    const uint32_t sbase = smem_to_u32(smem);
    const int tid = threadIdx.x, wid = tid >> 5, lane = tid & 31;
    const int rowBase = blockIdx.y * 128, colBase = blockIdx.x * 128;
    const int warpM = wid & 3, warpN = wid >> 2;     // 4x4 warp grid

    float acc[2][4][4];
    #pragma unroll
    for (int mt = 0; mt < 2; mt++)
        #pragma unroll
        for (int nt = 0; nt < 4; nt++)
            #pragma unroll
            for (int r = 0; r < 4; r++) acc[mt][nt][r] = 0.f;

    const int nch = K >> 6;

    // prefetch lambda (manual)
    #define PREFETCH(cc, buf) do { \
        const int k0_ = (cc) << 6; \
        const uint32_t sb_ = sbase + (buf) * STAGE; \
        _Pragma("unroll") \
        for (int i_ = 0; i_ < 2; i_++) { \
            const int s_ = tid + 512 * i_; \
            const int row_ = s_ >> 3, c_ = s_ & 7; \
            const uint32_t sw_ = SWZ((uint32_t)(row_ * 128 + c_ * 16)); \
            const size_t ao_ = (size_t)(rowBase + row_) * K + k0_ + c_ * 8; \
            const size_t wo_ = (size_t)(colBase + row_) * K + k0_ + c_ * 8; \
            CP_ASYNC16(sb_ + T_AHI + sw_, Ahi + ao_); \
            CP_ASYNC16(sb_ + T_ALO + sw_, Alo + ao_); \
            CP_ASYNC16(sb_ + T_WHI + sw_, Whi + wo_); \
            CP_ASYNC16(sb_ + T_WLO + sw_, Wlo + wo_); \
        } \
    } while (0)

    PREFETCH(0, 0); CP_COMMIT();

    for (int c = 0; c < nch; c++) {
        if (c + 1 < nch) { PREFETCH(c + 1, (c + 1) & 1); CP_COMMIT(); CP_WAIT1(); }
        else             { CP_WAIT0(); }
        __syncthreads();
        const uint32_t sb = sbase + (c & 1) * STAGE;

        #pragma unroll
        for (int ks = 0; ks < 4; ks++) {
            uint32_t ah[2][4], al[2][4];
            #pragma unroll
            for (int mt = 0; mt < 2; mt++) {
                const int r = warpM * 32 + mt * 16 + (lane & 15);
                const uint32_t off = SWZ((uint32_t)(r * 128 + ks * 32 + ((lane >> 4) << 4)));
                ldsm4(ah[mt][0], ah[mt][1], ah[mt][2], ah[mt][3], sb + T_AHI + off);
                ldsm4(al[mt][0], al[mt][1], al[mt][2], al[mt][3], sb + T_ALO + off);
            }
            uint32_t bh[4][2], bl[4][2];
            #pragma unroll
            for (int ng = 0; ng < 2; ng++) {
                const int r = warpN * 32 + ng * 16 + (lane & 7) + ((lane >> 4) << 3);
                const uint32_t off = SWZ((uint32_t)(r * 128 + ks * 32 + (((lane >> 3) & 1) << 4)));
                uint32_t q0, q1, q2, q3;
                ldsm4(q0, q1, q2, q3, sb + T_WHI + off);
                bh[ng * 2][0] = q0; bh[ng * 2][1] = q1;
                bh[ng * 2 + 1][0] = q2; bh[ng * 2 + 1][1] = q3;
                ldsm4(q0, q1, q2, q3, sb + T_WLO + off);
                bl[ng * 2][0] = q0; bl[ng * 2][1] = q1;
                bl[ng * 2 + 1][0] = q2; bl[ng * 2 + 1][1] = q3;
            }
            #pragma unroll
            for (int mt = 0; mt < 2; mt++)
                #pragma unroll
                for (int nt = 0; nt < 4; nt++) {
                    mma_bf16(acc[mt][nt], ah[mt], bh[nt]);
                    mma_bf16(acc[mt][nt], ah[mt], bl[nt]);
                    mma_bf16(acc[mt][nt], al[mt], bh[nt]);
                }
        }
        __syncthreads();
    }

    // epilogue
    #pragma unroll
    for (int mt = 0; mt < 2; mt++) {
        #pragma unroll
        for (int nt = 0; nt < 4; nt++) {
            const int col = colBase + warpN * 32 + nt * 8 + 2 * (lane & 3);
            const int row0 = rowBase + warpM * 32 + mt * 16 + (lane >> 2);
            const float bx = bias[col], by = bias[col + 1];
            #pragma unroll
            for (int h = 0; h < 2; h++) {
                const int row = row0 + h * 8;
                float v0 = acc[mt][nt][h * 2]     + bx;
                float v1 = acc[mt][nt][h * 2 + 1] + by;
                if (MODE == 2) {
                    v0 = fmaxf(v0, 0.f); v1 = fmaxf(v1, 0.f);
                    __nv_bfloat16 h0, l0, h1, l1;
                    split_hilo(v0, h0, l0); split_hilo(v1, h1, l1);
                    const size_t idx = ((size_t)row * N + col) >> 1;
                    ((uint32_t*)outHi)[idx] =
                        (uint32_t)__bfloat16_as_ushort(h0) | ((uint32_t)__bfloat16_as_ushort(h1) << 16);
                    ((uint32_t*)outLo)[idx] =
                        (uint32_t)__bfloat16_as_ushort(l0) | ((uint32_t)__bfloat16_as_ushort(l1) << 16);
                } else {
                    if (MODE == 1) {
                        const float2 rv = *(const float2*)&res[(size_t)row * N + col];
                        v0 += rv.x; v1 += rv.y;
                    }
                    float2 o = { v0, v1 };
                    *(float2*)&outF[(size_t)row * N + col] = o;
                }
            }
        }
    }
}

// ---------------- Attention scores: S[b,h] = Q[b,h] * K[b,h]^T / 8 -------------
__global__ void __launch_bounds__(256) scores_kernel(
    const float* __restrict__ Q, const float* __restrict__ Kg,
    float* __restrict__ Sc)
{
    const int bh = blockIdx.z;
    const int b = bh >> 4, h = bh & 15;
    const int q0 = blockIdx.y * 64, k0 = blockIdx.x * 64;
    __shared__ float Qs[64][68];
    __shared__ float Ks[64][68];
    const int tid = threadIdx.x;
    const size_t headOff = ((size_t)b * Ss) * Dd + (size_t)h * DKk;

    #pragma unroll
    for (int r = 0; r < 4; r++) {
        int f4  = tid + 256 * r;
        int row = f4 >> 4;
        int c4  = (f4 & 15) << 2;
        float4 qv = *(const float4*)(Q  + headOff + (size_t)(q0 + row) * Dd + c4);
        float4 kv = *(const float4*)(Kg + headOff + (size_t)(k0 + row) * Dd + c4);
        Qs[c4 + 0][row] = qv.x; Qs[c4 + 1][row] = qv.y;
        Qs[c4 + 2][row] = qv.z; Qs[c4 + 3][row] = qv.w;
        Ks[c4 + 0][row] = kv.x; Ks[c4 + 1][row] = kv.y;
        Ks[c4 + 2][row] = kv.z; Ks[c4 + 3][row] = kv.w;
    }
    __syncthreads();

    const int tx = tid & 15, ty = tid >> 4;
    float acc[4][4];
    #pragma unroll
    for (int i = 0; i < 4; i++)
        #pragma unroll
        for (int j = 0; j < 4; j++) acc[i][j] = 0.f;

    #pragma unroll 8
    for (int kk = 0; kk < 64; kk++) {
        float a[4], bv[4];
        *(float4*)a  = *(const float4*)&Qs[kk][ty * 4];
        *(float4*)bv = *(const float4*)&Ks[kk][tx * 4];
        #pragma unroll
        for (int i = 0; i < 4; i++)
            #pragma unroll
            for (int j = 0; j < 4; j++)
                acc[i][j] = fmaf(a[i], bv[j], acc[i][j]);
    }

    #pragma unroll
    for (int i = 0; i < 4; i++) {
        float* dst = Sc + ((size_t)bh * Ss + q0 + ty * 4 + i) * Ss + k0 + tx * 4;
        float4 o = { acc[i][0] * 0.125f, acc[i][1] * 0.125f,
                     acc[i][2] * 0.125f, acc[i][3] * 0.125f };
        *(float4*)dst = o;
    }
}

// ---------------- Row softmax over 1024 (in place) -----------------------------
__global__ void __launch_bounds__(256) softmax_kernel(float* __restrict__ Sc)
{
    float* p = Sc + (size_t)blockIdx.x * Ss;
    const int t = threadIdx.x;
    float v[4];
    float mx = -3.4e38f;
    #pragma unroll
    for (int i = 0; i < 4; i++) { v[i] = p[t + 256 * i]; mx = fmaxf(mx, v[i]); }
    __shared__ float rmax[8], rsum[8];
    __shared__ float bmax, binv;
    #pragma unroll
    for (int o = 16; o > 0; o >>= 1) mx = fmaxf(mx, __shfl_xor_sync(0xffffffffu, mx, o));
    if ((t & 31) == 0) rmax[t >> 5] = mx;
    __syncthreads();
    if (t == 0) {
        float m = rmax[0];
        #pragma unroll
        for (int i = 1; i < 8; i++) m = fmaxf(m, rmax[i]);
        bmax = m;
    }
    __syncthreads();
    mx = bmax;
    float sum = 0.f;
    #pragma unroll
    for (int i = 0; i < 4; i++) { v[i] = __expf(v[i] - mx); sum += v[i]; }
    #pragma unroll
    for (int o = 16; o > 0; o >>= 1) sum += __shfl_xor_sync(0xffffffffu, sum, o);
    if ((t & 31) == 0) rsum[t >> 5] = sum;
    __syncthreads();
    if (t == 0) {
        float s2 = 0.f;
        #pragma unroll
        for (int i = 0; i < 8; i++) s2 += rsum[i];
        binv = 1.f / s2;
    }
    __syncthreads();
    const float inv = binv;
    #pragma unroll
    for (int i = 0; i < 4; i++) p[t + 256 * i] = v[i] * inv;
}

// ---------------- PV: O[b,h] = P @ V, epilogue -> bf16 hi/lo --------------------
__global__ void __launch_bounds__(256) pv_kernel(
    const float* __restrict__ P, const float* __restrict__ V,
    __nv_bfloat16* __restrict__ Ohi, __nv_bfloat16* __restrict__ Olo)
{
    const int bh = blockIdx.y;
    const int b = bh >> 4, h = bh & 15;
    const int q0 = blockIdx.x * 128;
    const float* Pb = P + (size_t)bh * Ss * Ss;
    const size_t vOff = ((size_t)b * Ss) * Dd + (size_t)h * DKk;
    __shared__ float Ps[16][128];
    __shared__ float Vs[16][64];
    const int tid = threadIdx.x;
    const int tx = tid & 15, ty = tid >> 4;

    float acc[8][4];
    #pragma unroll
    for (int i = 0; i < 8; i++)
        #pragma unroll
        for (int j = 0; j < 4; j++) acc[i][j] = 0.f;

    for (int kb = 0; kb < Ss; kb += 16) {
        #pragma unroll
        for (int r = 0; r < 2; r++) {
            int f4  = tid + 256 * r;
            int row = f4 >> 2;
            int c4  = (f4 & 3) << 2;
            float4 pv = *(const float4*)(Pb + (size_t)(q0 + row) * Ss + kb + c4);
            Ps[c4 + 0][row] = pv.x; Ps[c4 + 1][row] = pv.y;
            Ps[c4 + 2][row] = pv.z; Ps[c4 + 3][row] = pv.w;
        }
        {
            int row = tid >> 4;
            int c4  = (tid & 15) << 2;
            *(float4*)&Vs[row][c4] =
                *(const float4*)(V + vOff + (size_t)(kb + row) * Dd + c4);
        }
        __syncthreads();
        #pragma unroll
        for (int kk = 0; kk < 16; kk++) {
            float a[8], bv[4];
            *(float4*)(a)     = *(const float4*)&Ps[kk][ty * 8];
            *(float4*)(a + 4) = *(const float4*)&Ps[kk][ty * 8 + 4];
            *(float4*)(bv)    = *(const float4*)&Vs[kk][tx * 4];
            #pragma unroll
            for (int i = 0; i < 8; i++)
                #pragma unroll
                for (int j = 0; j < 4; j++)
                    acc[i][j] = fmaf(a[i], bv[j], acc[i][j]);
        }
        __syncthreads();
    }
    #pragma unroll
    for (int i = 0; i < 8; i++) {
        const size_t idx = ((size_t)b * Ss + q0 + ty * 8 + i) * Dd + (size_t)h * DKk + tx * 4;
        __nv_bfloat16 h0, l0, h1, l1, h2, l2, h3, l3;
        split_hilo(acc[i][0], h0, l0); split_hilo(acc[i][1], h1, l1);
        split_hilo(acc[i][2], h2, l2); split_hilo(acc[i][3], h3, l3);
        uint32_t hA = (uint32_t)__bfloat16_as_ushort(h0) | ((uint32_t)__bfloat16_as_ushort(h1) << 16);
        uint32_t hB = (uint32_t)__bfloat16_as_ushort(h2) | ((uint32_t)__bfloat16_as_ushort(h3) << 16);
        uint32_t lA = (uint32_t)__bfloat16_as_ushort(l0) | ((uint32_t)__bfloat16_as_ushort(l1) << 16);
        uint32_t lB = (uint32_t)__bfloat16_as_ushort(l2) | ((uint32_t)__bfloat16_as_ushort(l3) << 16);
        *(uint2*)(Ohi + idx) = make_uint2(hA, hB);
        *(uint2*)(Olo + idx) = make_uint2(lA, lB);
    }
}

// ---------------- launch --------------------------------------------------------
extern "C" void kernel_launch(void* const* d_in, const int* in_sizes, int n_in,
                              void* d_out, int out_size)
{
    const float* x   = (const float*)d_in[0];
    const float* wq  = (const float*)d_in[2];
    const float* bq  = (const float*)d_in[3];
    const float* wk  = (const float*)d_in[4];
    const float* bk  = (const float*)d_in[5];
    const float* wv  = (const float*)d_in[6];
    const float* bv  = (const float*)d_in[7];
    const float* wo  = (const float*)d_in[8];
    const float* bo  = (const float*)d_in[9];
    const float* w1  = (const float*)d_in[10];
    const float* b1  = (const float*)d_in[11];
    const float* w2  = (const float*)d_in[12];
    const float* b2  = (const float*)d_in[13];
    const float* g1  = (const float*)d_in[14];
    const float* be1 = (const float*)d_in[15];
    const float* g2  = (const float*)d_in[16];
    const float* be2 = (const float*)d_in[17];
    float* out = (float*)d_out;

    float *q, *k, *v, *sc, *x1;
    __nv_bfloat16 *xnh, *xnl, *ath, *atl, *f1h, *f1l;
    __nv_bfloat16 *wqh, *wql, *wkh, *wkl, *wvh, *wvl, *woh, *wol, *w1h, *w1l, *w2h, *w2l;
    cudaGetSymbolAddress((void**)&q,   g_q);
    cudaGetSymbolAddress((void**)&k,   g_k);
    cudaGetSymbolAddress((void**)&v,   g_v);
    cudaGetSymbolAddress((void**)&sc,  g_sc);
    cudaGetSymbolAddress((void**)&x1,  g_x1);
    cudaGetSymbolAddress((void**)&xnh, g_xn_hi);  cudaGetSymbolAddress((void**)&xnl, g_xn_lo);
    cudaGetSymbolAddress((void**)&ath, g_at_hi);  cudaGetSymbolAddress((void**)&atl, g_at_lo);
    cudaGetSymbolAddress((void**)&f1h, g_f1_hi);  cudaGetSymbolAddress((void**)&f1l, g_f1_lo);
    cudaGetSymbolAddress((void**)&wqh, g_wq_hi);  cudaGetSymbolAddress((void**)&wql, g_wq_lo);
    cudaGetSymbolAddress((void**)&wkh, g_wk_hi);  cudaGetSymbolAddress((void**)&wkl, g_wk_lo);
    cudaGetSymbolAddress((void**)&wvh, g_wv_hi);  cudaGetSymbolAddress((void**)&wvl, g_wv_lo);
    cudaGetSymbolAddress((void**)&woh, g_wo_hi);  cudaGetSymbolAddress((void**)&wol, g_wo_lo);
    cudaGetSymbolAddress((void**)&w1h, g_w1_hi);  cudaGetSymbolAddress((void**)&w1l, g_w1_lo);
    cudaGetSymbolAddress((void**)&w2h, g_w2_hi);  cudaGetSymbolAddress((void**)&w2l, g_w2_lo);

    cudaFuncSetAttribute(gemm_mma<0>, cudaFuncAttributeMaxDynamicSharedMemorySize, GEMM_SMEM_DYN);
    cudaFuncSetAttribute(gemm_mma<1>, cudaFuncAttributeMaxDynamicSharedMemorySize, GEMM_SMEM_DYN);
    cudaFuncSetAttribute(gemm_mma<2>, cudaFuncAttributeMaxDynamicSharedMemorySize, GEMM_SMEM_DYN);

    // weight conversions
    const int nDD = Dd * Dd, nW1 = DFFf * Dd;
    conv_hilo<<<nDD / 1024, 256>>>(wq, wqh, wql, nDD / 4);
    conv_hilo<<<nDD / 1024, 256>>>(wk, wkh, wkl, nDD / 4);
    conv_hilo<<<nDD / 1024, 256>>>(wv, wvh, wvl, nDD / 4);
    conv_hilo<<<nDD / 1024, 256>>>(wo, woh, wol, nDD / 4);
    conv_hilo<<<nW1 / 1024, 256>>>(w1, w1h, w1l, nW1 / 4);
    conv_hilo<<<nW1 / 1024, 256>>>(w2, w2h, w2l, nW1 / 4);

    // LN1 -> hi/lo
    ln_kernel<<<MR, 256>>>(x, xnh, xnl, g1, be1);

    // QKV projections (tensor cores via mma.sync)
    gemm_mma<0><<<dim3(Dd/128, MR/128), 512, GEMM_SMEM_DYN>>>(
        xnh, xnl, wqh, wql, bq, nullptr, q, nullptr, nullptr, Dd, Dd);
    gemm_mma<0><<<dim3(Dd/128, MR/128), 512, GEMM_SMEM_DYN>>>(
        xnh, xnl, wkh, wkl, bk, nullptr, k, nullptr, nullptr, Dd, Dd);
    gemm_mma<0><<<dim3(Dd/128, MR/128), 512, GEMM_SMEM_DYN>>>(
        xnh, xnl, wvh, wvl, bv, nullptr, v, nullptr, nullptr, Dd, Dd);

    // attention
    scores_kernel<<<dim3(Ss/64, Ss/64, Bb*Hh), 256>>>(q, k, sc);
    softmax_kernel<<<Bb*Hh*Ss, 256>>>(sc);
    pv_kernel<<<dim3(Ss/128, Bb*Hh), 256>>>(sc, v, ath, atl);

    // output projection + residual
    gemm_mma<1><<<dim3(Dd/128, MR/128), 512, GEMM_SMEM_DYN>>>(
        ath, atl, woh, wol, bo, x, x1, nullptr, nullptr, Dd, Dd);

    // LN2 -> hi/lo
    ln_kernel<<<MR, 256>>>(x1, xnh, xnl, g2, be2);

    // FFN
    gemm_mma<2><<<dim3(DFFf/128, MR/128), 512, GEMM_SMEM_DYN>>>(
        xnh, xnl, w1h, w1l, b1, nullptr, nullptr, f1h, f1l, Dd, DFFf);
    gemm_mma<1><<<dim3(Dd/128, MR/128), 512, GEMM_SMEM_DYN>>>(
        f1h, f1l, w2h, w2l, b2, x1, out, nullptr, nullptr, DFFf, Dd);
}

// round 6
// speedup vs baseline: 3.2917x; 1.4333x over previous
#include <cuda_runtime.h>
#include <cuda_bf16.h>
#include <cstdint>

// Problem dims
#define Bb   8
#define Ss   1024
#define Dd   1024
#define Hh   16
#define DKk  64
#define DFFf 4096
#define MR   (Bb * Ss)   // 8192 rows

// ---------------- scratch (device globals; no allocations allowed) -------------
__device__ float g_x1  [(size_t)MR * Dd];

__device__ __nv_bfloat16 g_xn_hi[(size_t)MR * Dd];
__device__ __nv_bfloat16 g_xn_lo[(size_t)MR * Dd];
__device__ __nv_bfloat16 g_q_hi [(size_t)MR * Dd];
__device__ __nv_bfloat16 g_q_lo [(size_t)MR * Dd];
__device__ __nv_bfloat16 g_k_hi [(size_t)MR * Dd];
__device__ __nv_bfloat16 g_k_lo [(size_t)MR * Dd];
__device__ __nv_bfloat16 g_v_hi [(size_t)MR * Dd];
__device__ __nv_bfloat16 g_v_lo [(size_t)MR * Dd];
__device__ __nv_bfloat16 g_at_hi[(size_t)MR * Dd];
__device__ __nv_bfloat16 g_at_lo[(size_t)MR * Dd];
__device__ __nv_bfloat16 g_f1_hi[(size_t)MR * DFFf];
__device__ __nv_bfloat16 g_f1_lo[(size_t)MR * DFFf];
__device__ __nv_bfloat16 g_wq_hi[(size_t)Dd * Dd];
__device__ __nv_bfloat16 g_wq_lo[(size_t)Dd * Dd];
__device__ __nv_bfloat16 g_wk_hi[(size_t)Dd * Dd];
__device__ __nv_bfloat16 g_wk_lo[(size_t)Dd * Dd];
__device__ __nv_bfloat16 g_wv_hi[(size_t)Dd * Dd];
__device__ __nv_bfloat16 g_wv_lo[(size_t)Dd * Dd];
__device__ __nv_bfloat16 g_wo_hi[(size_t)Dd * Dd];
__device__ __nv_bfloat16 g_wo_lo[(size_t)Dd * Dd];
__device__ __nv_bfloat16 g_w1_hi[(size_t)DFFf * Dd];
__device__ __nv_bfloat16 g_w1_lo[(size_t)DFFf * Dd];
__device__ __nv_bfloat16 g_w2_hi[(size_t)Dd * DFFf];
__device__ __nv_bfloat16 g_w2_lo[(size_t)Dd * DFFf];

// ---------------- helpers -------------------------------------------------------
__device__ __forceinline__ uint32_t smem_to_u32(const void* p) {
    uint32_t a;
    asm("{ .reg .u64 t; cvta.to.shared.u64 t, %1; cvt.u32.u64 %0, t; }" : "=r"(a) : "l"(p));
    return a;
}
#define SWZ(off) ((off) ^ (((off) >> 3) & 0x70))

#define CP_ASYNC16(dst, src) \
    asm volatile("cp.async.cg.shared.global [%0], [%1], 16;" :: "r"(dst), "l"(src))
#define CP_COMMIT()  asm volatile("cp.async.commit_group;" ::: "memory")
#define CP_WAIT0()   asm volatile("cp.async.wait_group 0;" ::: "memory")
#define CP_WAIT1()   asm volatile("cp.async.wait_group 1;" ::: "memory")

__device__ __forceinline__ void ldsm4(uint32_t& r0, uint32_t& r1, uint32_t& r2, uint32_t& r3,
                                      uint32_t addr) {
    asm volatile("ldmatrix.sync.aligned.m8n8.x4.shared.b16 {%0,%1,%2,%3}, [%4];"
        : "=r"(r0), "=r"(r1), "=r"(r2), "=r"(r3) : "r"(addr));
}
__device__ __forceinline__ void ldsm4t(uint32_t& r0, uint32_t& r1, uint32_t& r2, uint32_t& r3,
                                       uint32_t addr) {
    asm volatile("ldmatrix.sync.aligned.m8n8.x4.trans.shared.b16 {%0,%1,%2,%3}, [%4];"
        : "=r"(r0), "=r"(r1), "=r"(r2), "=r"(r3) : "r"(addr));
}
__device__ __forceinline__ void mma_bf16(float* c, const uint32_t* a, const uint32_t* b) {
    asm volatile(
        "mma.sync.aligned.m16n8k16.row.col.f32.bf16.bf16.f32 "
        "{%0,%1,%2,%3}, {%4,%5,%6,%7}, {%8,%9}, {%0,%1,%2,%3};"
        : "+f"(c[0]), "+f"(c[1]), "+f"(c[2]), "+f"(c[3])
        : "r"(a[0]), "r"(a[1]), "r"(a[2]), "r"(a[3]), "r"(b[0]), "r"(b[1]));
}

__device__ __forceinline__ void split_hilo(float x, __nv_bfloat16& h, __nv_bfloat16& l) {
    h = __float2bfloat16(x);
    l = __float2bfloat16(x - __bfloat162float(h));
}
__device__ __forceinline__ uint32_t pack_hi2(float a, float b) {
    __nv_bfloat16 ha = __float2bfloat16(a), hb = __float2bfloat16(b);
    return (uint32_t)__bfloat16_as_ushort(ha) | ((uint32_t)__bfloat16_as_ushort(hb) << 16);
}
__device__ __forceinline__ void pack_hilo2(float a, float b, uint32_t& ph, uint32_t& pl) {
    __nv_bfloat16 ha, la, hb, lb;
    split_hilo(a, ha, la); split_hilo(b, hb, lb);
    ph = (uint32_t)__bfloat16_as_ushort(ha) | ((uint32_t)__bfloat16_as_ushort(hb) << 16);
    pl = (uint32_t)__bfloat16_as_ushort(la) | ((uint32_t)__bfloat16_as_ushort(lb) << 16);
}

// ---------------- LayerNorm -> bf16 hi/lo output -------------------------------
__global__ void __launch_bounds__(256) ln_kernel(
    const float* __restrict__ x,
    __nv_bfloat16* __restrict__ ohi, __nv_bfloat16* __restrict__ olo,
    const float* __restrict__ gamma, const float* __restrict__ beta)
{
    const int row = blockIdx.x;
    const float* xr = x + (size_t)row * Dd;
    float s = 0.f, sq = 0.f;
    for (int i = threadIdx.x; i < Dd; i += 256) {
        float v = xr[i]; s += v; sq += v * v;
    }
    #pragma unroll
    for (int o = 16; o > 0; o >>= 1) {
        s  += __shfl_xor_sync(0xffffffffu, s, o);
        sq += __shfl_xor_sync(0xffffffffu, sq, o);
    }
    __shared__ float rs[8], rq[8];
    __shared__ float bmu, brstd;
    const int w = threadIdx.x >> 5, l = threadIdx.x & 31;
    if (l == 0) { rs[w] = s; rq[w] = sq; }
    __syncthreads();
    if (threadIdx.x == 0) {
        float ts = 0.f, tq = 0.f;
        #pragma unroll
        for (int i = 0; i < 8; i++) { ts += rs[i]; tq += rq[i]; }
        float mu  = ts / (float)Dd;
        float var = (tq - (float)Dd * mu * mu) / (float)(Dd - 1);
        bmu = mu; brstd = rsqrtf(var + 1e-5f);
    }
    __syncthreads();
    const float g = gamma[0], be = beta[0];
    const float mu = bmu, rstd = brstd;
    for (int i = threadIdx.x; i < Dd; i += 256) {
        float v = g * (xr[i] - mu) * rstd + be;
        __nv_bfloat16 h, lo2;
        split_hilo(v, h, lo2);
        ohi[(size_t)row * Dd + i] = h;
        olo[(size_t)row * Dd + i] = lo2;
    }
}

// ---------------- fp32 -> bf16 hi/lo conversion (weights) ----------------------
__global__ void __launch_bounds__(256) conv_hilo(
    const float* __restrict__ x,
    __nv_bfloat16* __restrict__ hi, __nv_bfloat16* __restrict__ lo, int n4)
{
    int i = blockIdx.x * 256 + threadIdx.x;
    if (i >= n4) return;
    float4 v = ((const float4*)x)[i];
    uint32_t hA, lA, hB, lB;
    pack_hilo2(v.x, v.y, hA, lA);
    pack_hilo2(v.z, v.w, hB, lB);
    ((uint2*)hi)[i] = make_uint2(hA, hB);
    ((uint2*)lo)[i] = make_uint2(lA, lB);
}

// ---------------- split-bf16 mma.sync GEMM: C = A * W^T ------------------------
// MODE 0: out fp32 = acc + bias
// MODE 1: out fp32 = acc + bias + res
// MODE 2: relu(acc + bias) -> bf16 hi/lo
// MODE 3: (acc + bias)     -> bf16 hi/lo
#define T_AHI 0
#define T_ALO 16384
#define T_WHI 32768
#define T_WLO 49152
#define STAGE 65536
#define GEMM_SMEM_DYN 131072

template<int MODE>
__global__ void __launch_bounds__(512) gemm_mma(
    const __nv_bfloat16* __restrict__ Ahi, const __nv_bfloat16* __restrict__ Alo,
    const __nv_bfloat16* __restrict__ Whi, const __nv_bfloat16* __restrict__ Wlo,
    const float* __restrict__ bias, const float* __restrict__ res,
    float* __restrict__ outF,
    __nv_bfloat16* __restrict__ outHi, __nv_bfloat16* __restrict__ outLo,
    int K, int N)
{
    extern __shared__ char smem[];
    const uint32_t sbase = smem_to_u32(smem);
    const int tid = threadIdx.x, wid = tid >> 5, lane = tid & 31;
    const int rowBase = blockIdx.y * 128, colBase = blockIdx.x * 128;
    const int warpM = wid & 3, warpN = wid >> 2;     // 4x4 warp grid

    float acc[2][4][4];
    #pragma unroll
    for (int mt = 0; mt < 2; mt++)
        #pragma unroll
        for (int nt = 0; nt < 4; nt++)
            #pragma unroll
            for (int r = 0; r < 4; r++) acc[mt][nt][r] = 0.f;

    const int nch = K >> 6;

    #define PREFETCH(cc, buf) do { \
        const int k0_ = (cc) << 6; \
        const uint32_t sb_ = sbase + (buf) * STAGE; \
        _Pragma("unroll") \
        for (int i_ = 0; i_ < 2; i_++) { \
            const int s_ = tid + 512 * i_; \
            const int row_ = s_ >> 3, c_ = s_ & 7; \
            const uint32_t sw_ = SWZ((uint32_t)(row_ * 128 + c_ * 16)); \
            const size_t ao_ = (size_t)(rowBase + row_) * K + k0_ + c_ * 8; \
            const size_t wo_ = (size_t)(colBase + row_) * K + k0_ + c_ * 8; \
            CP_ASYNC16(sb_ + T_AHI + sw_, Ahi + ao_); \
            CP_ASYNC16(sb_ + T_ALO + sw_, Alo + ao_); \
            CP_ASYNC16(sb_ + T_WHI + sw_, Whi + wo_); \
            CP_ASYNC16(sb_ + T_WLO + sw_, Wlo + wo_); \
        } \
    } while (0)

    PREFETCH(0, 0); CP_COMMIT();

    for (int c = 0; c < nch; c++) {
        if (c + 1 < nch) { PREFETCH(c + 1, (c + 1) & 1); CP_COMMIT(); CP_WAIT1(); }
        else             { CP_WAIT0(); }
        __syncthreads();
        const uint32_t sb = sbase + (c & 1) * STAGE;

        #pragma unroll
        for (int ks = 0; ks < 4; ks++) {
            uint32_t ah[2][4], al[2][4];
            #pragma unroll
            for (int mt = 0; mt < 2; mt++) {
                const int r = warpM * 32 + mt * 16 + (lane & 15);
                const uint32_t off = SWZ((uint32_t)(r * 128 + ks * 32 + ((lane >> 4) << 4)));
                ldsm4(ah[mt][0], ah[mt][1], ah[mt][2], ah[mt][3], sb + T_AHI + off);
                ldsm4(al[mt][0], al[mt][1], al[mt][2], al[mt][3], sb + T_ALO + off);
            }
            uint32_t bh[4][2], bl[4][2];
            #pragma unroll
            for (int ng = 0; ng < 2; ng++) {
                const int r = warpN * 32 + ng * 16 + (lane & 7) + ((lane >> 4) << 3);
                const uint32_t off = SWZ((uint32_t)(r * 128 + ks * 32 + (((lane >> 3) & 1) << 4)));
                uint32_t q0, q1, q2, q3;
                ldsm4(q0, q1, q2, q3, sb + T_WHI + off);
                bh[ng * 2][0] = q0; bh[ng * 2][1] = q1;
                bh[ng * 2 + 1][0] = q2; bh[ng * 2 + 1][1] = q3;
                ldsm4(q0, q1, q2, q3, sb + T_WLO + off);
                bl[ng * 2][0] = q0; bl[ng * 2][1] = q1;
                bl[ng * 2 + 1][0] = q2; bl[ng * 2 + 1][1] = q3;
            }
            #pragma unroll
            for (int mt = 0; mt < 2; mt++)
                #pragma unroll
                for (int nt = 0; nt < 4; nt++) {
                    mma_bf16(acc[mt][nt], ah[mt], bh[nt]);
                    mma_bf16(acc[mt][nt], ah[mt], bl[nt]);
                    mma_bf16(acc[mt][nt], al[mt], bh[nt]);
                }
        }
        __syncthreads();
    }

    // epilogue
    #pragma unroll
    for (int mt = 0; mt < 2; mt++) {
        #pragma unroll
        for (int nt = 0; nt < 4; nt++) {
            const int col = colBase + warpN * 32 + nt * 8 + 2 * (lane & 3);
            const int row0 = rowBase + warpM * 32 + mt * 16 + (lane >> 2);
            const float bx = bias[col], by = bias[col + 1];
            #pragma unroll
            for (int h = 0; h < 2; h++) {
                const int row = row0 + h * 8;
                float v0 = acc[mt][nt][h * 2]     + bx;
                float v1 = acc[mt][nt][h * 2 + 1] + by;
                if (MODE >= 2) {
                    if (MODE == 2) { v0 = fmaxf(v0, 0.f); v1 = fmaxf(v1, 0.f); }
                    uint32_t ph, pl;
                    pack_hilo2(v0, v1, ph, pl);
                    const size_t idx = ((size_t)row * N + col) >> 1;
                    ((uint32_t*)outHi)[idx] = ph;
                    ((uint32_t*)outLo)[idx] = pl;
                } else {
                    if (MODE == 1) {
                        const float2 rv = *(const float2*)&res[(size_t)row * N + col];
                        v0 += rv.x; v1 += rv.y;
                    }
                    float2 o = { v0, v1 };
                    *(float2*)&outF[(size_t)row * N + col] = o;
                }
            }
        }
    }
}

// ---------------- Fused flash attention (split-bf16 mma.sync) ------------------
// Grid: (S/128, B*H). CTA: 256 thr = 8 warps; warp w owns q-rows [w*16, w*16+16).
// smem: Qhi Qlo Khi Klo Vhi Vlo, 16KB each (128 rows x 64 bf16, SW128 rows of 128B)
#define SQH 0
#define SQL 16384
#define SKH 32768
#define SKL 49152
#define SVH 65536
#define SVL 81920
#define ATT_SMEM_DYN 98304

__global__ void __launch_bounds__(256) attn_kernel(
    const __nv_bfloat16* __restrict__ Qh, const __nv_bfloat16* __restrict__ Ql,
    const __nv_bfloat16* __restrict__ Kh, const __nv_bfloat16* __restrict__ Kl,
    const __nv_bfloat16* __restrict__ Vh, const __nv_bfloat16* __restrict__ Vl,
    __nv_bfloat16* __restrict__ Oh, __nv_bfloat16* __restrict__ Ol)
{
    extern __shared__ char smem[];
    const uint32_t sb = smem_to_u32(smem);
    const int tid = threadIdx.x, wid = tid >> 5, lane = tid & 31;
    const int bh = blockIdx.y, b = bh >> 4, h = bh & 15;
    const int q0 = blockIdx.x * 128;
    const size_t qtok = (size_t)b * Ss + q0;
    const int hcol = h * DKk;
    const int qr = wid * 16;

    // load Q tile (hi/lo) once
    #pragma unroll
    for (int i = 0; i < 4; i++) {
        const int s = tid + 256 * i;
        const int row = s >> 3, ch = s & 7;
        const uint32_t sw = SWZ((uint32_t)(row * 128 + ch * 16));
        const size_t g = (qtok + row) * Dd + hcol + ch * 8;
        CP_ASYNC16(sb + SQH + sw, Qh + g);
        CP_ASYNC16(sb + SQL + sw, Ql + g);
    }
    CP_COMMIT();

    float accO[8][4];
    #pragma unroll
    for (int nt = 0; nt < 8; nt++)
        #pragma unroll
        for (int r = 0; r < 4; r++) accO[nt][r] = 0.f;
    float mrow[2] = { -1e30f, -1e30f };
    float lrow[2] = { 0.f, 0.f };

    for (int kt = 0; kt < 8; kt++) {
        __syncthreads();     // previous tile's smem reads complete
        #pragma unroll
        for (int i = 0; i < 4; i++) {
            const int s = tid + 256 * i;
            const int row = s >> 3, ch = s & 7;
            const uint32_t sw = SWZ((uint32_t)(row * 128 + ch * 16));
            const size_t g = ((size_t)b * Ss + kt * 128 + row) * Dd + hcol + ch * 8;
            CP_ASYNC16(sb + SKH + sw, Kh + g);
            CP_ASYNC16(sb + SKL + sw, Kl + g);
            CP_ASYNC16(sb + SVH + sw, Vh + g);
            CP_ASYNC16(sb + SVL + sw, Vl + g);
        }
        CP_COMMIT(); CP_WAIT0();
        __syncthreads();

        #pragma unroll
        for (int half = 0; half < 2; half++) {
            // ---- S = Q K^T over 64 keys ----
            float sacc[8][4];
            #pragma unroll
            for (int nt = 0; nt < 8; nt++)
                #pragma unroll
                for (int r = 0; r < 4; r++) sacc[nt][r] = 0.f;

            #pragma unroll
            for (int ks = 0; ks < 4; ks++) {
                uint32_t aqh[4], aql[4];
                {
                    const int r = qr + (lane & 15);
                    const uint32_t off = SWZ((uint32_t)(r * 128 + ks * 32 + ((lane >> 4) << 4)));
                    ldsm4(aqh[0], aqh[1], aqh[2], aqh[3], sb + SQH + off);
                    ldsm4(aql[0], aql[1], aql[2], aql[3], sb + SQL + off);
                }
                #pragma unroll
                for (int np = 0; np < 4; np++) {
                    const int r = half * 64 + np * 16 + (lane & 7) + ((lane >> 4) << 3);
                    const uint32_t off = SWZ((uint32_t)(r * 128 + ks * 32 + (((lane >> 3) & 1) << 4)));
                    uint32_t kh0, kh1, kh2, kh3, kl0, kl1, kl2, kl3;
                    ldsm4(kh0, kh1, kh2, kh3, sb + SKH + off);
                    ldsm4(kl0, kl1, kl2, kl3, sb + SKL + off);
                    uint32_t bH0[2] = { kh0, kh1 }, bH1[2] = { kh2, kh3 };
                    uint32_t bL0[2] = { kl0, kl1 }, bL1[2] = { kl2, kl3 };
                    mma_bf16(sacc[np * 2],     aqh, bH0);
                    mma_bf16(sacc[np * 2],     aqh, bL0);
                    mma_bf16(sacc[np * 2],     aql, bH0);
                    mma_bf16(sacc[np * 2 + 1], aqh, bH1);
                    mma_bf16(sacc[np * 2 + 1], aqh, bL1);
                    mma_bf16(sacc[np * 2 + 1], aql, bH1);
                }
            }
            // scale 1/sqrt(64)
            #pragma unroll
            for (int nt = 0; nt < 8; nt++)
                #pragma unroll
                for (int r = 0; r < 4; r++) sacc[nt][r] *= 0.125f;

            // ---- online softmax (two row groups: lane>>2 and +8) ----
            float mx0 = -1e30f, mx1 = -1e30f;
            #pragma unroll
            for (int nt = 0; nt < 8; nt++) {
                mx0 = fmaxf(mx0, fmaxf(sacc[nt][0], sacc[nt][1]));
                mx1 = fmaxf(mx1, fmaxf(sacc[nt][2], sacc[nt][3]));
            }
            mx0 = fmaxf(mx0, __shfl_xor_sync(0xffffffffu, mx0, 1));
            mx0 = fmaxf(mx0, __shfl_xor_sync(0xffffffffu, mx0, 2));
            mx1 = fmaxf(mx1, __shfl_xor_sync(0xffffffffu, mx1, 1));
            mx1 = fmaxf(mx1, __shfl_xor_sync(0xffffffffu, mx1, 2));
            const float nm0 = fmaxf(mrow[0], mx0), nm1 = fmaxf(mrow[1], mx1);
            const float al0 = __expf(mrow[0] - nm0), al1 = __expf(mrow[1] - nm1);
            mrow[0] = nm0; mrow[1] = nm1;
            float sum0 = 0.f, sum1 = 0.f;
            #pragma unroll
            for (int nt = 0; nt < 8; nt++) {
                sacc[nt][0] = __expf(sacc[nt][0] - nm0);
                sacc[nt][1] = __expf(sacc[nt][1] - nm0);
                sacc[nt][2] = __expf(sacc[nt][2] - nm1);
                sacc[nt][3] = __expf(sacc[nt][3] - nm1);
                sum0 += sacc[nt][0] + sacc[nt][1];
                sum1 += sacc[nt][2] + sacc[nt][3];
                accO[nt][0] *= al0; accO[nt][1] *= al0;
                accO[nt][2] *= al1; accO[nt][3] *= al1;
            }
            sum0 += __shfl_xor_sync(0xffffffffu, sum0, 1);
            sum0 += __shfl_xor_sync(0xffffffffu, sum0, 2);
            sum1 += __shfl_xor_sync(0xffffffffu, sum1, 1);
            sum1 += __shfl_xor_sync(0xffffffffu, sum1, 2);
            lrow[0] = lrow[0] * al0 + sum0;
            lrow[1] = lrow[1] * al1 + sum1;

            // ---- O += P V ----
            #pragma unroll
            for (int t = 0; t < 4; t++) {
                uint32_t pah[4], pal[4];
                pack_hilo2(sacc[2 * t][0],     sacc[2 * t][1],     pah[0], pal[0]);
                pack_hilo2(sacc[2 * t][2],     sacc[2 * t][3],     pah[1], pal[1]);
                pack_hilo2(sacc[2 * t + 1][0], sacc[2 * t + 1][1], pah[2], pal[2]);
                pack_hilo2(sacc[2 * t + 1][2], sacc[2 * t + 1][3], pah[3], pal[3]);
                const int k0 = half * 64 + t * 16;
                #pragma unroll
                for (int np = 0; np < 4; np++) {
                    const int krow = k0 + (lane & 15);
                    const int col = np * 16 + ((lane >> 4) << 3);
                    const uint32_t off = SWZ((uint32_t)(krow * 128 + col * 2));
                    uint32_t vh0, vh1, vh2, vh3, vl0, vl1, vl2, vl3;
                    ldsm4t(vh0, vh1, vh2, vh3, sb + SVH + off);
                    ldsm4t(vl0, vl1, vl2, vl3, sb + SVL + off);
                    uint32_t bH0[2] = { vh0, vh1 }, bH1[2] = { vh2, vh3 };
                    uint32_t bL0[2] = { vl0, vl1 }, bL1[2] = { vl2, vl3 };
                    mma_bf16(accO[np * 2],     pah, bH0);
                    mma_bf16(accO[np * 2],     pah, bL0);
                    mma_bf16(accO[np * 2],     pal, bH0);
                    mma_bf16(accO[np * 2 + 1], pah, bH1);
                    mma_bf16(accO[np * 2 + 1], pah, bL1);
                    mma_bf16(accO[np * 2 + 1], pal, bH1);
                }
            }
        }
    }

    // ---- epilogue: O / l -> bf16 hi/lo gmem ----
    const float inv0 = 1.f / lrow[0], inv1 = 1.f / lrow[1];
    #pragma unroll
    for (int nt = 0; nt < 8; nt++) {
        const int col = hcol + nt * 8 + 2 * (lane & 3);
        #pragma unroll
        for (int g = 0; g < 2; g++) {
            const size_t tok = qtok + qr + (lane >> 2) + g * 8;
            const float inv = g ? inv1 : inv0;
            uint32_t ph, pl;
            pack_hilo2(accO[nt][2 * g] * inv, accO[nt][2 * g + 1] * inv, ph, pl);
            const size_t idx = (tok * Dd + col) >> 1;
            ((uint32_t*)Oh)[idx] = ph;
            ((uint32_t*)Ol)[idx] = pl;
        }
    }
}

// ---------------- launch --------------------------------------------------------
extern "C" void kernel_launch(void* const* d_in, const int* in_sizes, int n_in,
                              void* d_out, int out_size)
{
    const float* x   = (const float*)d_in[0];
    const float* wq  = (const float*)d_in[2];
    const float* bq  = (const float*)d_in[3];
    const float* wk  = (const float*)d_in[4];
    const float* bk  = (const float*)d_in[5];
    const float* wv  = (const float*)d_in[6];
    const float* bv  = (const float*)d_in[7];
    const float* wo  = (const float*)d_in[8];
    const float* bo  = (const float*)d_in[9];
    const float* w1  = (const float*)d_in[10];
    const float* b1  = (const float*)d_in[11];
    const float* w2  = (const float*)d_in[12];
    const float* b2  = (const float*)d_in[13];
    const float* g1  = (const float*)d_in[14];
    const float* be1 = (const float*)d_in[15];
    const float* g2  = (const float*)d_in[16];
    const float* be2 = (const float*)d_in[17];
    float* out = (float*)d_out;

    float* x1;
    __nv_bfloat16 *xnh, *xnl, *qh, *ql, *kh, *kl, *vh, *vl, *ath, *atl, *f1h, *f1l;
    __nv_bfloat16 *wqh, *wql, *wkh, *wkl, *wvh, *wvl, *woh, *wol, *w1h, *w1l, *w2h, *w2l;
    cudaGetSymbolAddress((void**)&x1,  g_x1);
    cudaGetSymbolAddress((void**)&xnh, g_xn_hi);  cudaGetSymbolAddress((void**)&xnl, g_xn_lo);
    cudaGetSymbolAddress((void**)&qh,  g_q_hi);   cudaGetSymbolAddress((void**)&ql,  g_q_lo);
    cudaGetSymbolAddress((void**)&kh,  g_k_hi);   cudaGetSymbolAddress((void**)&kl,  g_k_lo);
    cudaGetSymbolAddress((void**)&vh,  g_v_hi);   cudaGetSymbolAddress((void**)&vl,  g_v_lo);
    cudaGetSymbolAddress((void**)&ath, g_at_hi);  cudaGetSymbolAddress((void**)&atl, g_at_lo);
    cudaGetSymbolAddress((void**)&f1h, g_f1_hi);  cudaGetSymbolAddress((void**)&f1l, g_f1_lo);
    cudaGetSymbolAddress((void**)&wqh, g_wq_hi);  cudaGetSymbolAddress((void**)&wql, g_wq_lo);
    cudaGetSymbolAddress((void**)&wkh, g_wk_hi);  cudaGetSymbolAddress((void**)&wkl, g_wk_lo);
    cudaGetSymbolAddress((void**)&wvh, g_wv_hi);  cudaGetSymbolAddress((void**)&wvl, g_wv_lo);
    cudaGetSymbolAddress((void**)&woh, g_wo_hi);  cudaGetSymbolAddress((void**)&wol, g_wo_lo);
    cudaGetSymbolAddress((void**)&w1h, g_w1_hi);  cudaGetSymbolAddress((void**)&w1l, g_w1_lo);
    cudaGetSymbolAddress((void**)&w2h, g_w2_hi);  cudaGetSymbolAddress((void**)&w2l, g_w2_lo);

    cudaFuncSetAttribute(gemm_mma<0>, cudaFuncAttributeMaxDynamicSharedMemorySize, GEMM_SMEM_DYN);
    cudaFuncSetAttribute(gemm_mma<1>, cudaFuncAttributeMaxDynamicSharedMemorySize, GEMM_SMEM_DYN);
    cudaFuncSetAttribute(gemm_mma<2>, cudaFuncAttributeMaxDynamicSharedMemorySize, GEMM_SMEM_DYN);
    cudaFuncSetAttribute(gemm_mma<3>, cudaFuncAttributeMaxDynamicSharedMemorySize, GEMM_SMEM_DYN);
    cudaFuncSetAttribute(attn_kernel, cudaFuncAttributeMaxDynamicSharedMemorySize, ATT_SMEM_DYN);

    // weight conversions
    const int nDD = Dd * Dd, nW1 = DFFf * Dd;
    conv_hilo<<<nDD / 1024, 256>>>(wq, wqh, wql, nDD / 4);
    conv_hilo<<<nDD / 1024, 256>>>(wk, wkh, wkl, nDD / 4);
    conv_hilo<<<nDD / 1024, 256>>>(wv, wvh, wvl, nDD / 4);
    conv_hilo<<<nDD / 1024, 256>>>(wo, woh, wol, nDD / 4);
    conv_hilo<<<nW1 / 1024, 256>>>(w1, w1h, w1l, nW1 / 4);
    conv_hilo<<<nW1 / 1024, 256>>>(w2, w2h, w2l, nW1 / 4);

    // LN1 -> hi/lo
    ln_kernel<<<MR, 256>>>(x, xnh, xnl, g1, be1);

    // QKV projections -> bf16 hi/lo
    gemm_mma<3><<<dim3(Dd/128, MR/128), 512, GEMM_SMEM_DYN>>>(
        xnh, xnl, wqh, wql, bq, nullptr, nullptr, qh, ql, Dd, Dd);
    gemm_mma<3><<<dim3(Dd/128, MR/128), 512, GEMM_SMEM_DYN>>>(
        xnh, xnl, wkh, wkl, bk, nullptr, nullptr, kh, kl, Dd, Dd);
    gemm_mma<3><<<dim3(Dd/128, MR/128), 512, GEMM_SMEM_DYN>>>(
        xnh, xnl, wvh, wvl, bv, nullptr, nullptr, vh, vl, Dd, Dd);

    // fused flash attention
    attn_kernel<<<dim3(Ss/128, Bb*Hh), 256, ATT_SMEM_DYN>>>(
        qh, ql, kh, kl, vh, vl, ath, atl);

    // output projection + residual
    gemm_mma<1><<<dim3(Dd/128, MR/128), 512, GEMM_SMEM_DYN>>>(
        ath, atl, woh, wol, bo, x, x1, nullptr, nullptr, Dd, Dd);

    // LN2 -> hi/lo
    ln_kernel<<<MR, 256>>>(x1, xnh, xnl, g2, be2);

    // FFN
    gemm_mma<2><<<dim3(DFFf/128, MR/128), 512, GEMM_SMEM_DYN>>>(
        xnh, xnl, w1h, w1l, b1, nullptr, nullptr, f1h, f1l, Dd, DFFf);
    gemm_mma<1><<<dim3(Dd/128, MR/128), 512, GEMM_SMEM_DYN>>>(
        f1h, f1l, w2h, w2l, b2, x1, out, nullptr, nullptr, DFFf, Dd);
}

// round 7
// speedup vs baseline: 3.3750x; 1.0253x over previous
#include <cuda_runtime.h>
#include <cuda_bf16.h>
#include <cstdint>

// Problem dims
#define Bb   8
#define Ss   1024
#define Dd   1024
#define Hh   16
#define DKk  64
#define DFFf 4096
#define MR   (Bb * Ss)   // 8192 rows
#define QKVN 3072

// ---------------- scratch (device globals; no allocations allowed) -------------
__device__ float g_x1  [(size_t)MR * Dd];

__device__ __nv_bfloat16 g_xn_hi [(size_t)MR * Dd];
__device__ __nv_bfloat16 g_xn_lo [(size_t)MR * Dd];
__device__ __nv_bfloat16 g_qkv_hi[(size_t)MR * QKVN];
__device__ __nv_bfloat16 g_qkv_lo[(size_t)MR * QKVN];
__device__ __nv_bfloat16 g_at_hi [(size_t)MR * Dd];
__device__ __nv_bfloat16 g_at_lo [(size_t)MR * Dd];
__device__ __nv_bfloat16 g_f1_hi [(size_t)MR * DFFf];
__device__ __nv_bfloat16 g_f1_lo [(size_t)MR * DFFf];
__device__ __nv_bfloat16 g_wqkv_hi[(size_t)QKVN * Dd];
__device__ __nv_bfloat16 g_wqkv_lo[(size_t)QKVN * Dd];
__device__ __nv_bfloat16 g_wo_hi[(size_t)Dd * Dd];
__device__ __nv_bfloat16 g_wo_lo[(size_t)Dd * Dd];
__device__ __nv_bfloat16 g_w1_hi[(size_t)DFFf * Dd];
__device__ __nv_bfloat16 g_w1_lo[(size_t)DFFf * Dd];
__device__ __nv_bfloat16 g_w2_hi[(size_t)Dd * DFFf];
__device__ __nv_bfloat16 g_w2_lo[(size_t)Dd * DFFf];
__device__ float g_bqkv[QKVN];

// ---------------- helpers -------------------------------------------------------
__device__ __forceinline__ uint32_t smem_to_u32(const void* p) {
    uint32_t a;
    asm("{ .reg .u64 t; cvta.to.shared.u64 t, %1; cvt.u32.u64 %0, t; }" : "=r"(a) : "l"(p));
    return a;
}
#define SWZ(off) ((off) ^ (((off) >> 3) & 0x70))

#define CP_ASYNC16(dst, src) \
    asm volatile("cp.async.cg.shared.global [%0], [%1], 16;" :: "r"(dst), "l"(src))
#define CP_COMMIT()  asm volatile("cp.async.commit_group;" ::: "memory")
#define CP_WAIT0()   asm volatile("cp.async.wait_group 0;" ::: "memory")
#define CP_WAIT1()   asm volatile("cp.async.wait_group 1;" ::: "memory")

__device__ __forceinline__ void ldsm4(uint32_t& r0, uint32_t& r1, uint32_t& r2, uint32_t& r3,
                                      uint32_t addr) {
    asm volatile("ldmatrix.sync.aligned.m8n8.x4.shared.b16 {%0,%1,%2,%3}, [%4];"
        : "=r"(r0), "=r"(r1), "=r"(r2), "=r"(r3) : "r"(addr));
}
__device__ __forceinline__ void ldsm4t(uint32_t& r0, uint32_t& r1, uint32_t& r2, uint32_t& r3,
                                       uint32_t addr) {
    asm volatile("ldmatrix.sync.aligned.m8n8.x4.trans.shared.b16 {%0,%1,%2,%3}, [%4];"
        : "=r"(r0), "=r"(r1), "=r"(r2), "=r"(r3) : "r"(addr));
}
__device__ __forceinline__ void mma_bf16(float* c, const uint32_t* a, const uint32_t* b) {
    asm volatile(
        "mma.sync.aligned.m16n8k16.row.col.f32.bf16.bf16.f32 "
        "{%0,%1,%2,%3}, {%4,%5,%6,%7}, {%8,%9}, {%0,%1,%2,%3};"
        : "+f"(c[0]), "+f"(c[1]), "+f"(c[2]), "+f"(c[3])
        : "r"(a[0]), "r"(a[1]), "r"(a[2]), "r"(a[3]), "r"(b[0]), "r"(b[1]));
}

__device__ __forceinline__ void split_hilo(float x, __nv_bfloat16& h, __nv_bfloat16& l) {
    h = __float2bfloat16(x);
    l = __float2bfloat16(x - __bfloat162float(h));
}
__device__ __forceinline__ void pack_hilo2(float a, float b, uint32_t& ph, uint32_t& pl) {
    __nv_bfloat16 ha, la, hb, lb;
    split_hilo(a, ha, la); split_hilo(b, hb, lb);
    ph = (uint32_t)__bfloat16_as_ushort(ha) | ((uint32_t)__bfloat16_as_ushort(hb) << 16);
    pl = (uint32_t)__bfloat16_as_ushort(la) | ((uint32_t)__bfloat16_as_ushort(lb) << 16);
}

// ---------------- LayerNorm -> bf16 hi/lo output -------------------------------
__global__ void __launch_bounds__(256) ln_kernel(
    const float* __restrict__ x,
    __nv_bfloat16* __restrict__ ohi, __nv_bfloat16* __restrict__ olo,
    const float* __restrict__ gamma, const float* __restrict__ beta)
{
    const int row = blockIdx.x;
    const float* xr = x + (size_t)row * Dd;
    float s = 0.f, sq = 0.f;
    for (int i = threadIdx.x; i < Dd; i += 256) {
        float v = xr[i]; s += v; sq += v * v;
    }
    #pragma unroll
    for (int o = 16; o > 0; o >>= 1) {
        s  += __shfl_xor_sync(0xffffffffu, s, o);
        sq += __shfl_xor_sync(0xffffffffu, sq, o);
    }
    __shared__ float rs[8], rq[8];
    __shared__ float bmu, brstd;
    const int w = threadIdx.x >> 5, l = threadIdx.x & 31;
    if (l == 0) { rs[w] = s; rq[w] = sq; }
    __syncthreads();
    if (threadIdx.x == 0) {
        float ts = 0.f, tq = 0.f;
        #pragma unroll
        for (int i = 0; i < 8; i++) { ts += rs[i]; tq += rq[i]; }
        float mu  = ts / (float)Dd;
        float var = (tq - (float)Dd * mu * mu) / (float)(Dd - 1);
        bmu = mu; brstd = rsqrtf(var + 1e-5f);
    }
    __syncthreads();
    const float g = gamma[0], be = beta[0];
    const float mu = bmu, rstd = brstd;
    for (int i = threadIdx.x; i < Dd; i += 256) {
        float v = g * (xr[i] - mu) * rstd + be;
        __nv_bfloat16 h, lo2;
        split_hilo(v, h, lo2);
        ohi[(size_t)row * Dd + i] = h;
        olo[(size_t)row * Dd + i] = lo2;
    }
}

// ---------------- fp32 -> bf16 hi/lo conversion (weights), 16 floats/thread -----
__global__ void __launch_bounds__(256) conv_hilo(
    const float* __restrict__ x,
    __nv_bfloat16* __restrict__ hi, __nv_bfloat16* __restrict__ lo, int n4)
{
    const int base = (blockIdx.x * 256 + threadIdx.x) * 4;
    #pragma unroll
    for (int u = 0; u < 4; u++) {
        const int i = base + u;
        if (i >= n4) return;
        float4 v = ((const float4*)x)[i];
        uint32_t hA, lA, hB, lB;
        pack_hilo2(v.x, v.y, hA, lA);
        pack_hilo2(v.z, v.w, hB, lB);
        ((uint2*)hi)[i] = make_uint2(hA, hB);
        ((uint2*)lo)[i] = make_uint2(lA, lB);
    }
}

// ---------------- pack Q/K/V biases into one vector ----------------------------
__global__ void pack_bias(const float* __restrict__ b0, const float* __restrict__ b1,
                          const float* __restrict__ b2, float* __restrict__ dst)
{
    const int i = blockIdx.x * 256 + threadIdx.x;
    if (i < Dd) { dst[i] = b0[i]; dst[Dd + i] = b1[i]; dst[2 * Dd + i] = b2[i]; }
}

// ---------------- split-bf16 mma.sync GEMM: C = A * W^T ------------------------
// MODE 0: out fp32 = acc + bias
// MODE 1: out fp32 = acc + bias + res
// MODE 2: relu(acc + bias) -> bf16 hi/lo
// MODE 3: (acc + bias)     -> bf16 hi/lo
#define T_AHI 0
#define T_ALO 16384
#define T_WHI 32768
#define T_WLO 49152
#define STAGE 65536
#define GEMM_SMEM_DYN 196608   // 3 stages

template<int MODE>
__global__ void __launch_bounds__(512) gemm_mma(
    const __nv_bfloat16* __restrict__ Ahi, const __nv_bfloat16* __restrict__ Alo,
    const __nv_bfloat16* __restrict__ Whi, const __nv_bfloat16* __restrict__ Wlo,
    const float* __restrict__ bias, const float* __restrict__ res,
    float* __restrict__ outF,
    __nv_bfloat16* __restrict__ outHi, __nv_bfloat16* __restrict__ outLo,
    int K, int N)
{
    extern __shared__ char smem[];
    const uint32_t sbase = smem_to_u32(smem);
    const int tid = threadIdx.x, wid = tid >> 5, lane = tid & 31;
    const int rowBase = blockIdx.y * 128, colBase = blockIdx.x * 128;
    const int warpM = wid & 3, warpN = wid >> 2;     // 4x4 warp grid

    float acc[2][4][4];
    #pragma unroll
    for (int mt = 0; mt < 2; mt++)
        #pragma unroll
        for (int nt = 0; nt < 4; nt++)
            #pragma unroll
            for (int r = 0; r < 4; r++) acc[mt][nt][r] = 0.f;

    const int nch = K >> 6;

    #define PREFETCH(cc, buf) do { \
        const int k0_ = (cc) << 6; \
        const uint32_t sb_ = sbase + (buf) * STAGE; \
        _Pragma("unroll") \
        for (int i_ = 0; i_ < 2; i_++) { \
            const int s_ = tid + 512 * i_; \
            const int row_ = s_ >> 3, c_ = s_ & 7; \
            const uint32_t sw_ = SWZ((uint32_t)(row_ * 128 + c_ * 16)); \
            const size_t ao_ = (size_t)(rowBase + row_) * K + k0_ + c_ * 8; \
            const size_t wo_ = (size_t)(colBase + row_) * K + k0_ + c_ * 8; \
            CP_ASYNC16(sb_ + T_AHI + sw_, Ahi + ao_); \
            CP_ASYNC16(sb_ + T_ALO + sw_, Alo + ao_); \
            CP_ASYNC16(sb_ + T_WHI + sw_, Whi + wo_); \
            CP_ASYNC16(sb_ + T_WLO + sw_, Wlo + wo_); \
        } \
    } while (0)

    PREFETCH(0, 0); CP_COMMIT();
    PREFETCH(1, 1); CP_COMMIT();

    int buf = 0;
    for (int c = 0; c < nch; c++) {
        if (c < nch - 1) CP_WAIT1(); else CP_WAIT0();
        __syncthreads();
        if (c + 2 < nch) {
            int nb = buf + 2; if (nb >= 3) nb -= 3;
            PREFETCH(c + 2, nb); CP_COMMIT();
        }
        const uint32_t sb = sbase + buf * STAGE;

        #pragma unroll
        for (int ks = 0; ks < 4; ks++) {
            uint32_t ah[2][4], al[2][4];
            #pragma unroll
            for (int mt = 0; mt < 2; mt++) {
                const int r = warpM * 32 + mt * 16 + (lane & 15);
                const uint32_t off = SWZ((uint32_t)(r * 128 + ks * 32 + ((lane >> 4) << 4)));
                ldsm4(ah[mt][0], ah[mt][1], ah[mt][2], ah[mt][3], sb + T_AHI + off);
                ldsm4(al[mt][0], al[mt][1], al[mt][2], al[mt][3], sb + T_ALO + off);
            }
            uint32_t bh[4][2], bl[4][2];
            #pragma unroll
            for (int ng = 0; ng < 2; ng++) {
                const int r = warpN * 32 + ng * 16 + (lane & 7) + ((lane >> 4) << 3);
                const uint32_t off = SWZ((uint32_t)(r * 128 + ks * 32 + (((lane >> 3) & 1) << 4)));
                uint32_t q0, q1, q2, q3;
                ldsm4(q0, q1, q2, q3, sb + T_WHI + off);
                bh[ng * 2][0] = q0; bh[ng * 2][1] = q1;
                bh[ng * 2 + 1][0] = q2; bh[ng * 2 + 1][1] = q3;
                ldsm4(q0, q1, q2, q3, sb + T_WLO + off);
                bl[ng * 2][0] = q0; bl[ng * 2][1] = q1;
                bl[ng * 2 + 1][0] = q2; bl[ng * 2 + 1][1] = q3;
            }
            #pragma unroll
            for (int mt = 0; mt < 2; mt++)
                #pragma unroll
                for (int nt = 0; nt < 4; nt++) {
                    mma_bf16(acc[mt][nt], ah[mt], bh[nt]);
                    mma_bf16(acc[mt][nt], ah[mt], bl[nt]);
                    mma_bf16(acc[mt][nt], al[mt], bh[nt]);
                }
        }
        buf++; if (buf >= 3) buf = 0;
    }

    // epilogue
    #pragma unroll
    for (int mt = 0; mt < 2; mt++) {
        #pragma unroll
        for (int nt = 0; nt < 4; nt++) {
            const int col = colBase + warpN * 32 + nt * 8 + 2 * (lane & 3);
            const int row0 = rowBase + warpM * 32 + mt * 16 + (lane >> 2);
            const float bx = bias[col], by = bias[col + 1];
            #pragma unroll
            for (int h = 0; h < 2; h++) {
                const int row = row0 + h * 8;
                float v0 = acc[mt][nt][h * 2]     + bx;
                float v1 = acc[mt][nt][h * 2 + 1] + by;
                if (MODE >= 2) {
                    if (MODE == 2) { v0 = fmaxf(v0, 0.f); v1 = fmaxf(v1, 0.f); }
                    uint32_t ph, pl;
                    pack_hilo2(v0, v1, ph, pl);
                    const size_t idx = ((size_t)row * N + col) >> 1;
                    ((uint32_t*)outHi)[idx] = ph;
                    ((uint32_t*)outLo)[idx] = pl;
                } else {
                    if (MODE == 1) {
                        const float2 rv = *(const float2*)&res[(size_t)row * N + col];
                        v0 += rv.x; v1 += rv.y;
                    }
                    float2 o = { v0, v1 };
                    *(float2*)&outF[(size_t)row * N + col] = o;
                }
            }
        }
    }
}

// ---------------- Fused flash attention (split-bf16 mma.sync) ------------------
// Reads packed QKV (row stride 3072). Grid: (S/128, B*H). 256 thr = 8 warps.
// smem: Q hi/lo 32KB + 3 KV stages x 64KB {KH,KL,VH,VL 16KB each} = 224KB
#define SQH 0
#define SQL 16384
#define KV0 32768
#define KVSTG 65536
#define AKH 0
#define AKL 16384
#define AVH 32768
#define AVL 49152
#define ATT_SMEM_DYN 229376

__global__ void __launch_bounds__(256) attn_kernel(
    const __nv_bfloat16* __restrict__ QKVh, const __nv_bfloat16* __restrict__ QKVl,
    __nv_bfloat16* __restrict__ Oh, __nv_bfloat16* __restrict__ Ol)
{
    extern __shared__ char smem[];
    const uint32_t sb = smem_to_u32(smem);
    const int tid = threadIdx.x, wid = tid >> 5, lane = tid & 31;
    const int bh = blockIdx.y, b = bh >> 4, h = bh & 15;
    const int q0 = blockIdx.x * 128;
    const size_t qtok = (size_t)b * Ss + q0;
    const int hcol = h * DKk;
    const int qr = wid * 16;

    #define PREFETCH_KV(kt_, buf_) do { \
        const uint32_t kvb_ = sb + KV0 + (buf_) * KVSTG; \
        _Pragma("unroll") \
        for (int i_ = 0; i_ < 4; i_++) { \
            const int s_ = tid + 256 * i_; \
            const int row_ = s_ >> 3, ch_ = s_ & 7; \
            const uint32_t sw_ = SWZ((uint32_t)(row_ * 128 + ch_ * 16)); \
            const size_t gk_ = ((size_t)b * Ss + (kt_) * 128 + row_) * QKVN + Dd + hcol + ch_ * 8; \
            CP_ASYNC16(kvb_ + AKH + sw_, QKVh + gk_); \
            CP_ASYNC16(kvb_ + AKL + sw_, QKVl + gk_); \
            CP_ASYNC16(kvb_ + AVH + sw_, QKVh + gk_ + Dd); \
            CP_ASYNC16(kvb_ + AVL + sw_, QKVl + gk_ + Dd); \
        } \
    } while (0)

    // group 0: Q + KV tile 0; group 1: KV tile 1
    #pragma unroll
    for (int i = 0; i < 4; i++) {
        const int s = tid + 256 * i;
        const int row = s >> 3, ch = s & 7;
        const uint32_t sw = SWZ((uint32_t)(row * 128 + ch * 16));
        const size_t g = (qtok + row) * QKVN + hcol + ch * 8;
        CP_ASYNC16(sb + SQH + sw, QKVh + g);
        CP_ASYNC16(sb + SQL + sw, QKVl + g);
    }
    PREFETCH_KV(0, 0); CP_COMMIT();
    PREFETCH_KV(1, 1); CP_COMMIT();

    float accO[8][4];
    #pragma unroll
    for (int nt = 0; nt < 8; nt++)
        #pragma unroll
        for (int r = 0; r < 4; r++) accO[nt][r] = 0.f;
    float mrow[2] = { -1e30f, -1e30f };
    float lrow[2] = { 0.f, 0.f };

    int buf = 0;
    for (int kt = 0; kt < 8; kt++) {
        if (kt < 7) CP_WAIT1(); else CP_WAIT0();
        __syncthreads();
        if (kt + 2 < 8) {
            int nb = buf + 2; if (nb >= 3) nb -= 3;
            PREFETCH_KV(kt + 2, nb); CP_COMMIT();
        }
        const uint32_t kvb = sb + KV0 + buf * KVSTG;

        #pragma unroll
        for (int half = 0; half < 2; half++) {
            // ---- S = Q K^T over 64 keys ----
            float sacc[8][4];
            #pragma unroll
            for (int nt = 0; nt < 8; nt++)
                #pragma unroll
                for (int r = 0; r < 4; r++) sacc[nt][r] = 0.f;

            #pragma unroll
            for (int ks = 0; ks < 4; ks++) {
                uint32_t aqh[4], aql[4];
                {
                    const int r = qr + (lane & 15);
                    const uint32_t off = SWZ((uint32_t)(r * 128 + ks * 32 + ((lane >> 4) << 4)));
                    ldsm4(aqh[0], aqh[1], aqh[2], aqh[3], sb + SQH + off);
                    ldsm4(aql[0], aql[1], aql[2], aql[3], sb + SQL + off);
                }
                #pragma unroll
                for (int np = 0; np < 4; np++) {
                    const int r = half * 64 + np * 16 + (lane & 7) + ((lane >> 4) << 3);
                    const uint32_t off = SWZ((uint32_t)(r * 128 + ks * 32 + (((lane >> 3) & 1) << 4)));
                    uint32_t kh0, kh1, kh2, kh3, kl0, kl1, kl2, kl3;
                    ldsm4(kh0, kh1, kh2, kh3, kvb + AKH + off);
                    ldsm4(kl0, kl1, kl2, kl3, kvb + AKL + off);
                    uint32_t bH0[2] = { kh0, kh1 }, bH1[2] = { kh2, kh3 };
                    uint32_t bL0[2] = { kl0, kl1 }, bL1[2] = { kl2, kl3 };
                    mma_bf16(sacc[np * 2],     aqh, bH0);
                    mma_bf16(sacc[np * 2],     aqh, bL0);
                    mma_bf16(sacc[np * 2],     aql, bH0);
                    mma_bf16(sacc[np * 2 + 1], aqh, bH1);
                    mma_bf16(sacc[np * 2 + 1], aqh, bL1);
                    mma_bf16(sacc[np * 2 + 1], aql, bH1);
                }
            }
            #pragma unroll
            for (int nt = 0; nt < 8; nt++)
                #pragma unroll
                for (int r = 0; r < 4; r++) sacc[nt][r] *= 0.125f;

            // ---- online softmax ----
            float mx0 = -1e30f, mx1 = -1e30f;
            #pragma unroll
            for (int nt = 0; nt < 8; nt++) {
                mx0 = fmaxf(mx0, fmaxf(sacc[nt][0], sacc[nt][1]));
                mx1 = fmaxf(mx1, fmaxf(sacc[nt][2], sacc[nt][3]));
            }
            mx0 = fmaxf(mx0, __shfl_xor_sync(0xffffffffu, mx0, 1));
            mx0 = fmaxf(mx0, __shfl_xor_sync(0xffffffffu, mx0, 2));
            mx1 = fmaxf(mx1, __shfl_xor_sync(0xffffffffu, mx1, 1));
            mx1 = fmaxf(mx1, __shfl_xor_sync(0xffffffffu, mx1, 2));
            const float nm0 = fmaxf(mrow[0], mx0), nm1 = fmaxf(mrow[1], mx1);
            const float al0 = __expf(mrow[0] - nm0), al1 = __expf(mrow[1] - nm1);
            mrow[0] = nm0; mrow[1] = nm1;
            float sum0 = 0.f, sum1 = 0.f;
            #pragma unroll
            for (int nt = 0; nt < 8; nt++) {
                sacc[nt][0] = __expf(sacc[nt][0] - nm0);
                sacc[nt][1] = __expf(sacc[nt][1] - nm0);
                sacc[nt][2] = __expf(sacc[nt][2] - nm1);
                sacc[nt][3] = __expf(sacc[nt][3] - nm1);
                sum0 += sacc[nt][0] + sacc[nt][1];
                sum1 += sacc[nt][2] + sacc[nt][3];
                accO[nt][0] *= al0; accO[nt][1] *= al0;
                accO[nt][2] *= al1; accO[nt][3] *= al1;
            }
            sum0 += __shfl_xor_sync(0xffffffffu, sum0, 1);
            sum0 += __shfl_xor_sync(0xffffffffu, sum0, 2);
            sum1 += __shfl_xor_sync(0xffffffffu, sum1, 1);
            sum1 += __shfl_xor_sync(0xffffffffu, sum1, 2);
            lrow[0] = lrow[0] * al0 + sum0;
            lrow[1] = lrow[1] * al1 + sum1;

            // ---- O += P V ----
            #pragma unroll
            for (int t = 0; t < 4; t++) {
                uint32_t pah[4], pal[4];
                pack_hilo2(sacc[2 * t][0],     sacc[2 * t][1],     pah[0], pal[0]);
                pack_hilo2(sacc[2 * t][2],     sacc[2 * t][3],     pah[1], pal[1]);
                pack_hilo2(sacc[2 * t + 1][0], sacc[2 * t + 1][1], pah[2], pal[2]);
                pack_hilo2(sacc[2 * t + 1][2], sacc[2 * t + 1][3], pah[3], pal[3]);
                const int k0 = half * 64 + t * 16;
                #pragma unroll
                for (int np = 0; np < 4; np++) {
                    const int krow = k0 + (lane & 15);
                    const int col = np * 16 + ((lane >> 4) << 3);
                    const uint32_t off = SWZ((uint32_t)(krow * 128 + col * 2));
                    uint32_t vh0, vh1, vh2, vh3, vl0, vl1, vl2, vl3;
                    ldsm4t(vh0, vh1, vh2, vh3, kvb + AVH + off);
                    ldsm4t(vl0, vl1, vl2, vl3, kvb + AVL + off);
                    uint32_t bH0[2] = { vh0, vh1 }, bH1[2] = { vh2, vh3 };
                    uint32_t bL0[2] = { vl0, vl1 }, bL1[2] = { vl2, vl3 };
                    mma_bf16(accO[np * 2],     pah, bH0);
                    mma_bf16(accO[np * 2],     pah, bL0);
                    mma_bf16(accO[np * 2],     pal, bH0);
                    mma_bf16(accO[np * 2 + 1], pah, bH1);
                    mma_bf16(accO[np * 2 + 1], pah, bL1);
                    mma_bf16(accO[np * 2 + 1], pal, bH1);
                }
            }
        }
        buf++; if (buf >= 3) buf = 0;
    }

    // ---- epilogue: O / l -> bf16 hi/lo gmem (stride Dd) ----
    const float inv0 = 1.f / lrow[0], inv1 = 1.f / lrow[1];
    #pragma unroll
    for (int nt = 0; nt < 8; nt++) {
        const int col = hcol + nt * 8 + 2 * (lane & 3);
        #pragma unroll
        for (int g = 0; g < 2; g++) {
            const size_t tok = qtok + qr + (lane >> 2) + g * 8;
            const float inv = g ? inv1 : inv0;
            uint32_t ph, pl;
            pack_hilo2(accO[nt][2 * g] * inv, accO[nt][2 * g + 1] * inv, ph, pl);
            const size_t idx = (tok * Dd + col) >> 1;
            ((uint32_t*)Oh)[idx] = ph;
            ((uint32_t*)Ol)[idx] = pl;
        }
    }
}

// ---------------- launch --------------------------------------------------------
extern "C" void kernel_launch(void* const* d_in, const int* in_sizes, int n_in,
                              void* d_out, int out_size)
{
    const float* x   = (const float*)d_in[0];
    const float* wq  = (const float*)d_in[2];
    const float* bq  = (const float*)d_in[3];
    const float* wk  = (const float*)d_in[4];
    const float* bk  = (const float*)d_in[5];
    const float* wv  = (const float*)d_in[6];
    const float* bv  = (const float*)d_in[7];
    const float* wo  = (const float*)d_in[8];
    const float* bo  = (const float*)d_in[9];
    const float* w1  = (const float*)d_in[10];
    const float* b1  = (const float*)d_in[11];
    const float* w2  = (const float*)d_in[12];
    const float* b2  = (const float*)d_in[13];
    const float* g1  = (const float*)d_in[14];
    const float* be1 = (const float*)d_in[15];
    const float* g2  = (const float*)d_in[16];
    const float* be2 = (const float*)d_in[17];
    float* out = (float*)d_out;

    float *x1, *bqkv;
    __nv_bfloat16 *xnh, *xnl, *qkvh, *qkvl, *ath, *atl, *f1h, *f1l;
    __nv_bfloat16 *wqkvh, *wqkvl, *woh, *wol, *w1h, *w1l, *w2h, *w2l;
    cudaGetSymbolAddress((void**)&x1,    g_x1);
    cudaGetSymbolAddress((void**)&bqkv,  g_bqkv);
    cudaGetSymbolAddress((void**)&xnh,   g_xn_hi);   cudaGetSymbolAddress((void**)&xnl,  g_xn_lo);
    cudaGetSymbolAddress((void**)&qkvh,  g_qkv_hi);  cudaGetSymbolAddress((void**)&qkvl, g_qkv_lo);
    cudaGetSymbolAddress((void**)&ath,   g_at_hi);   cudaGetSymbolAddress((void**)&atl,  g_at_lo);
    cudaGetSymbolAddress((void**)&f1h,   g_f1_hi);   cudaGetSymbolAddress((void**)&f1l,  g_f1_lo);
    cudaGetSymbolAddress((void**)&wqkvh, g_wqkv_hi); cudaGetSymbolAddress((void**)&wqkvl, g_wqkv_lo);
    cudaGetSymbolAddress((void**)&woh,   g_wo_hi);   cudaGetSymbolAddress((void**)&wol,  g_wo_lo);
    cudaGetSymbolAddress((void**)&w1h,   g_w1_hi);   cudaGetSymbolAddress((void**)&w1l,  g_w1_lo);
    cudaGetSymbolAddress((void**)&w2h,   g_w2_hi);   cudaGetSymbolAddress((void**)&w2l,  g_w2_lo);

    cudaFuncSetAttribute(gemm_mma<0>, cudaFuncAttributeMaxDynamicSharedMemorySize, GEMM_SMEM_DYN);
    cudaFuncSetAttribute(gemm_mma<1>, cudaFuncAttributeMaxDynamicSharedMemorySize, GEMM_SMEM_DYN);
    cudaFuncSetAttribute(gemm_mma<2>, cudaFuncAttributeMaxDynamicSharedMemorySize, GEMM_SMEM_DYN);
    cudaFuncSetAttribute(gemm_mma<3>, cudaFuncAttributeMaxDynamicSharedMemorySize, GEMM_SMEM_DYN);
    cudaFuncSetAttribute(attn_kernel, cudaFuncAttributeMaxDynamicSharedMemorySize, ATT_SMEM_DYN);

    // weight conversions (wq/wk/wv packed into one [3072 x 1024] buffer)
    const int nDD = Dd * Dd, nW1 = DFFf * Dd;
    conv_hilo<<<nDD / 4096, 256>>>(wq, wqkvh,                 wqkvl,                 nDD / 4);
    conv_hilo<<<nDD / 4096, 256>>>(wk, wqkvh + (size_t)nDD,   wqkvl + (size_t)nDD,   nDD / 4);
    conv_hilo<<<nDD / 4096, 256>>>(wv, wqkvh + (size_t)2*nDD, wqkvl + (size_t)2*nDD, nDD / 4);
    conv_hilo<<<nDD / 4096, 256>>>(wo, woh, wol, nDD / 4);
    conv_hilo<<<nW1 / 4096, 256>>>(w1, w1h, w1l, nW1 / 4);
    conv_hilo<<<nW1 / 4096, 256>>>(w2, w2h, w2l, nW1 / 4);
    pack_bias<<<Dd / 256, 256>>>(bq, bk, bv, bqkv);

    // LN1 -> hi/lo
    ln_kernel<<<MR, 256>>>(x, xnh, xnl, g1, be1);

    // fused QKV projection -> packed bf16 hi/lo [MR x 3072]
    gemm_mma<3><<<dim3(QKVN/128, MR/128), 512, GEMM_SMEM_DYN>>>(
        xnh, xnl, wqkvh, wqkvl, bqkv, nullptr, nullptr, qkvh, qkvl, Dd, QKVN);

    // fused flash attention
    attn_kernel<<<dim3(Ss/128, Bb*Hh), 256, ATT_SMEM_DYN>>>(qkvh, qkvl, ath, atl);

    // output projection + residual
    gemm_mma<1><<<dim3(Dd/128, MR/128), 512, GEMM_SMEM_DYN>>>(
        ath, atl, woh, wol, bo, x, x1, nullptr, nullptr, Dd, Dd);

    // LN2 -> hi/lo
    ln_kernel<<<MR, 256>>>(x1, xnh, xnl, g2, be2);

    // FFN
    gemm_mma<2><<<dim3(DFFf/128, MR/128), 512, GEMM_SMEM_DYN>>>(
        xnh, xnl, w1h, w1l, b1, nullptr, nullptr, f1h, f1l, Dd, DFFf);
    gemm_mma<1><<<dim3(Dd/128, MR/128), 512, GEMM_SMEM_DYN>>>(
        f1h, f1l, w2h, w2l, b2, x1, out, nullptr, nullptr, DFFf, Dd);
}

// round 8
// speedup vs baseline: 4.6790x; 1.3864x over previous
#include <cuda_runtime.h>
#include <cuda_fp16.h>
#include <cstdint>

// Problem dims
#define Bb   8
#define Ss   1024
#define Dd   1024
#define Hh   16
#define DKk  64
#define DFFf 4096
#define MR   (Bb * Ss)   // 8192 rows
#define QKVN 3072

// ---------------- scratch (device globals; no allocations allowed) -------------
__device__ float g_x1  [(size_t)MR * Dd];

__device__ __half g_xn_hi [(size_t)MR * Dd];
__device__ __half g_qkv_hi[(size_t)MR * QKVN];
__device__ __half g_qkv_lo[(size_t)MR * QKVN];
__device__ __half g_at_hi [(size_t)MR * Dd];
__device__ __half g_f1_hi [(size_t)MR * DFFf];
__device__ __half g_wqkv_hi[(size_t)QKVN * Dd];
__device__ __half g_wqkv_lo[(size_t)QKVN * Dd];
__device__ __half g_wo_hi[(size_t)Dd * Dd];
__device__ __half g_wo_lo[(size_t)Dd * Dd];
__device__ __half g_w1_hi[(size_t)DFFf * Dd];
__device__ __half g_w1_lo[(size_t)DFFf * Dd];
__device__ __half g_w2_hi[(size_t)Dd * DFFf];
__device__ __half g_w2_lo[(size_t)Dd * DFFf];
__device__ float g_bqkv[QKVN];

// ---------------- helpers -------------------------------------------------------
__device__ __forceinline__ uint32_t smem_to_u32(const void* p) {
    uint32_t a;
    asm("{ .reg .u64 t; cvta.to.shared.u64 t, %1; cvt.u32.u64 %0, t; }" : "=r"(a) : "l"(p));
    return a;
}
#define SWZ(off) ((off) ^ (((off) >> 3) & 0x70))

#define CP_ASYNC16(dst, src) \
    asm volatile("cp.async.cg.shared.global [%0], [%1], 16;" :: "r"(dst), "l"(src))
#define CP_COMMIT()  asm volatile("cp.async.commit_group;" ::: "memory")
#define CP_WAIT0()   asm volatile("cp.async.wait_group 0;" ::: "memory")
#define CP_WAIT1()   asm volatile("cp.async.wait_group 1;" ::: "memory")

__device__ __forceinline__ void ldsm4(uint32_t& r0, uint32_t& r1, uint32_t& r2, uint32_t& r3,
                                      uint32_t addr) {
    asm volatile("ldmatrix.sync.aligned.m8n8.x4.shared.b16 {%0,%1,%2,%3}, [%4];"
        : "=r"(r0), "=r"(r1), "=r"(r2), "=r"(r3) : "r"(addr));
}
__device__ __forceinline__ void ldsm4t(uint32_t& r0, uint32_t& r1, uint32_t& r2, uint32_t& r3,
                                       uint32_t addr) {
    asm volatile("ldmatrix.sync.aligned.m8n8.x4.trans.shared.b16 {%0,%1,%2,%3}, [%4];"
        : "=r"(r0), "=r"(r1), "=r"(r2), "=r"(r3) : "r"(addr));
}
__device__ __forceinline__ void mma_f16(float* c, const uint32_t* a, const uint32_t* b) {
    asm volatile(
        "mma.sync.aligned.m16n8k16.row.col.f32.f16.f16.f32 "
        "{%0,%1,%2,%3}, {%4,%5,%6,%7}, {%8,%9}, {%0,%1,%2,%3};"
        : "+f"(c[0]), "+f"(c[1]), "+f"(c[2]), "+f"(c[3])
        : "r"(a[0]), "r"(a[1]), "r"(a[2]), "r"(a[3]), "r"(b[0]), "r"(b[1]));
}

__device__ __forceinline__ void split_hilo(float x, __half& h, __half& l) {
    h = __float2half_rn(x);
    l = __float2half_rn(x - __half2float(h));
}
__device__ __forceinline__ uint32_t pack_h2(float a, float b) {
    __half ha = __float2half_rn(a), hb = __float2half_rn(b);
    return (uint32_t)__half_as_ushort(ha) | ((uint32_t)__half_as_ushort(hb) << 16);
}
__device__ __forceinline__ void pack_hilo2(float a, float b, uint32_t& ph, uint32_t& pl) {
    __half ha, la, hb, lb;
    split_hilo(a, ha, la); split_hilo(b, hb, lb);
    ph = (uint32_t)__half_as_ushort(ha) | ((uint32_t)__half_as_ushort(hb) << 16);
    pl = (uint32_t)__half_as_ushort(la) | ((uint32_t)__half_as_ushort(lb) << 16);
}

// ---------------- LayerNorm -> fp16 hi output ----------------------------------
__global__ void __launch_bounds__(256) ln_kernel(
    const float* __restrict__ x, __half* __restrict__ ohi,
    const float* __restrict__ gamma, const float* __restrict__ beta)
{
    const int row = blockIdx.x;
    const float* xr = x + (size_t)row * Dd;
    float s = 0.f, sq = 0.f;
    for (int i = threadIdx.x; i < Dd; i += 256) {
        float v = xr[i]; s += v; sq += v * v;
    }
    #pragma unroll
    for (int o = 16; o > 0; o >>= 1) {
        s  += __shfl_xor_sync(0xffffffffu, s, o);
        sq += __shfl_xor_sync(0xffffffffu, sq, o);
    }
    __shared__ float rs[8], rq[8];
    __shared__ float bmu, brstd;
    const int w = threadIdx.x >> 5, l = threadIdx.x & 31;
    if (l == 0) { rs[w] = s; rq[w] = sq; }
    __syncthreads();
    if (threadIdx.x == 0) {
        float ts = 0.f, tq = 0.f;
        #pragma unroll
        for (int i = 0; i < 8; i++) { ts += rs[i]; tq += rq[i]; }
        float mu  = ts / (float)Dd;
        float var = (tq - (float)Dd * mu * mu) / (float)(Dd - 1);
        bmu = mu; brstd = rsqrtf(var + 1e-5f);
    }
    __syncthreads();
    const float g = gamma[0], be = beta[0];
    const float mu = bmu, rstd = brstd;
    for (int i = threadIdx.x; i < Dd; i += 256)
        ohi[(size_t)row * Dd + i] = __float2half_rn(g * (xr[i] - mu) * rstd + be);
}

// ---------------- fp32 -> fp16 hi/lo conversion (weights) ----------------------
__global__ void __launch_bounds__(256) conv_hilo(
    const float* __restrict__ x,
    __half* __restrict__ hi, __half* __restrict__ lo, int n4)
{
    const int base = (blockIdx.x * 256 + threadIdx.x) * 4;
    #pragma unroll
    for (int u = 0; u < 4; u++) {
        const int i = base + u;
        if (i >= n4) return;
        float4 v = ((const float4*)x)[i];
        uint32_t hA, lA, hB, lB;
        pack_hilo2(v.x, v.y, hA, lA);
        pack_hilo2(v.z, v.w, hB, lB);
        ((uint2*)hi)[i] = make_uint2(hA, hB);
        ((uint2*)lo)[i] = make_uint2(lA, lB);
    }
}

// ---------------- pack Q/K/V biases into one vector ----------------------------
__global__ void pack_bias(const float* __restrict__ b0, const float* __restrict__ b1,
                          const float* __restrict__ b2, float* __restrict__ dst)
{
    const int i = blockIdx.x * 256 + threadIdx.x;
    if (i < Dd) { dst[i] = b0[i]; dst[Dd + i] = b1[i]; dst[2 * Dd + i] = b2[i]; }
}

// ---------------- 2-product fp16 mma GEMM: C = A_hi * (W_hi + W_lo)^T ----------
// MODE 1: out fp32 = acc + bias + res
// MODE 2: relu(acc + bias) -> fp16 hi
// MODE 3: (acc + bias)     -> fp16 hi/lo
#define T_AHI 0
#define T_WHI 16384
#define T_WLO 32768
#define STAGE 49152
#define GEMM_SMEM_DYN 147456   // 3 stages

template<int MODE>
__global__ void __launch_bounds__(512) gemm_mma(
    const __half* __restrict__ Ah,
    const __half* __restrict__ Wh, const __half* __restrict__ Wl,
    const float* __restrict__ bias, const float* __restrict__ res,
    float* __restrict__ outF,
    __half* __restrict__ outHi, __half* __restrict__ outLo,
    int K, int N)
{
    extern __shared__ char smem[];
    const uint32_t sbase = smem_to_u32(smem);
    const int tid = threadIdx.x, wid = tid >> 5, lane = tid & 31;
    const int rowBase = blockIdx.y * 128, colBase = blockIdx.x * 128;
    const int warpM = wid & 3, warpN = wid >> 2;     // 4x4 warp grid

    float acc[2][4][4];
    #pragma unroll
    for (int mt = 0; mt < 2; mt++)
        #pragma unroll
        for (int nt = 0; nt < 4; nt++)
            #pragma unroll
            for (int r = 0; r < 4; r++) acc[mt][nt][r] = 0.f;

    const int nch = K >> 6;

    #define PREFETCH(cc, buf) do { \
        const int k0_ = (cc) << 6; \
        const uint32_t sb_ = sbase + (buf) * STAGE; \
        _Pragma("unroll") \
        for (int i_ = 0; i_ < 2; i_++) { \
            const int s_ = tid + 512 * i_; \
            const int row_ = s_ >> 3, c_ = s_ & 7; \
            const uint32_t sw_ = SWZ((uint32_t)(row_ * 128 + c_ * 16)); \
            const size_t ao_ = (size_t)(rowBase + row_) * K + k0_ + c_ * 8; \
            const size_t wo_ = (size_t)(colBase + row_) * K + k0_ + c_ * 8; \
            CP_ASYNC16(sb_ + T_AHI + sw_, Ah + ao_); \
            CP_ASYNC16(sb_ + T_WHI + sw_, Wh + wo_); \
            CP_ASYNC16(sb_ + T_WLO + sw_, Wl + wo_); \
        } \
    } while (0)

    PREFETCH(0, 0); CP_COMMIT();
    PREFETCH(1, 1); CP_COMMIT();

    int buf = 0;
    for (int c = 0; c < nch; c++) {
        if (c < nch - 1) CP_WAIT1(); else CP_WAIT0();
        __syncthreads();
        if (c + 2 < nch) {
            int nb = buf + 2; if (nb >= 3) nb -= 3;
            PREFETCH(c + 2, nb); CP_COMMIT();
        }
        const uint32_t sb = sbase + buf * STAGE;

        #pragma unroll
        for (int ks = 0; ks < 4; ks++) {
            uint32_t ah[2][4];
            #pragma unroll
            for (int mt = 0; mt < 2; mt++) {
                const int r = warpM * 32 + mt * 16 + (lane & 15);
                const uint32_t off = SWZ((uint32_t)(r * 128 + ks * 32 + ((lane >> 4) << 4)));
                ldsm4(ah[mt][0], ah[mt][1], ah[mt][2], ah[mt][3], sb + T_AHI + off);
            }
            uint32_t bh[4][2], bl[4][2];
            #pragma unroll
            for (int ng = 0; ng < 2; ng++) {
                const int r = warpN * 32 + ng * 16 + (lane & 7) + ((lane >> 4) << 3);
                const uint32_t off = SWZ((uint32_t)(r * 128 + ks * 32 + (((lane >> 3) & 1) << 4)));
                uint32_t q0, q1, q2, q3;
                ldsm4(q0, q1, q2, q3, sb + T_WHI + off);
                bh[ng * 2][0] = q0; bh[ng * 2][1] = q1;
                bh[ng * 2 + 1][0] = q2; bh[ng * 2 + 1][1] = q3;
                ldsm4(q0, q1, q2, q3, sb + T_WLO + off);
                bl[ng * 2][0] = q0; bl[ng * 2][1] = q1;
                bl[ng * 2 + 1][0] = q2; bl[ng * 2 + 1][1] = q3;
            }
            #pragma unroll
            for (int mt = 0; mt < 2; mt++)
                #pragma unroll
                for (int nt = 0; nt < 4; nt++) {
                    mma_f16(acc[mt][nt], ah[mt], bh[nt]);
                    mma_f16(acc[mt][nt], ah[mt], bl[nt]);
                }
        }
        buf++; if (buf >= 3) buf = 0;
    }

    // epilogue
    #pragma unroll
    for (int mt = 0; mt < 2; mt++) {
        #pragma unroll
        for (int nt = 0; nt < 4; nt++) {
            const int col = colBase + warpN * 32 + nt * 8 + 2 * (lane & 3);
            const int row0 = rowBase + warpM * 32 + mt * 16 + (lane >> 2);
            const float bx = bias[col], by = bias[col + 1];
            #pragma unroll
            for (int h = 0; h < 2; h++) {
                const int row = row0 + h * 8;
                float v0 = acc[mt][nt][h * 2]     + bx;
                float v1 = acc[mt][nt][h * 2 + 1] + by;
                if (MODE == 2) {
                    v0 = fmaxf(v0, 0.f); v1 = fmaxf(v1, 0.f);
                    ((uint32_t*)outHi)[((size_t)row * N + col) >> 1] = pack_h2(v0, v1);
                } else if (MODE == 3) {
                    uint32_t ph, pl;
                    pack_hilo2(v0, v1, ph, pl);
                    const size_t idx = ((size_t)row * N + col) >> 1;
                    ((uint32_t*)outHi)[idx] = ph;
                    ((uint32_t*)outLo)[idx] = pl;
                } else {
                    const float2 rv = *(const float2*)&res[(size_t)row * N + col];
                    float2 o = { v0 + rv.x, v1 + rv.y };
                    *(float2*)&outF[(size_t)row * N + col] = o;
                }
            }
        }
    }
}

// ---------------- Fused flash attention (2-product fp16 mma) -------------------
// Q hi-only 16KB + 3 KV stages x 64KB {KH,KL,VH,VL} = 208 KB
#define SQH 0
#define KV0 16384
#define KVSTG 65536
#define AKH 0
#define AKL 16384
#define AVH 32768
#define AVL 49152
#define ATT_SMEM_DYN 212992

__global__ void __launch_bounds__(256) attn_kernel(
    const __half* __restrict__ QKVh, const __half* __restrict__ QKVl,
    __half* __restrict__ Oh)
{
    extern __shared__ char smem[];
    const uint32_t sb = smem_to_u32(smem);
    const int tid = threadIdx.x, wid = tid >> 5, lane = tid & 31;
    const int bh = blockIdx.y, b = bh >> 4, h = bh & 15;
    const int q0 = blockIdx.x * 128;
    const size_t qtok = (size_t)b * Ss + q0;
    const int hcol = h * DKk;
    const int qr = wid * 16;

    #define PREFETCH_KV(kt_, buf_) do { \
        const uint32_t kvb_ = sb + KV0 + (buf_) * KVSTG; \
        _Pragma("unroll") \
        for (int i_ = 0; i_ < 4; i_++) { \
            const int s_ = tid + 256 * i_; \
            const int row_ = s_ >> 3, ch_ = s_ & 7; \
            const uint32_t sw_ = SWZ((uint32_t)(row_ * 128 + ch_ * 16)); \
            const size_t gk_ = ((size_t)b * Ss + (kt_) * 128 + row_) * QKVN + Dd + hcol + ch_ * 8; \
            CP_ASYNC16(kvb_ + AKH + sw_, QKVh + gk_); \
            CP_ASYNC16(kvb_ + AKL + sw_, QKVl + gk_); \
            CP_ASYNC16(kvb_ + AVH + sw_, QKVh + gk_ + Dd); \
            CP_ASYNC16(kvb_ + AVL + sw_, QKVl + gk_ + Dd); \
        } \
    } while (0)

    #pragma unroll
    for (int i = 0; i < 4; i++) {
        const int s = tid + 256 * i;
        const int row = s >> 3, ch = s & 7;
        const uint32_t sw = SWZ((uint32_t)(row * 128 + ch * 16));
        CP_ASYNC16(sb + SQH + sw, QKVh + (qtok + row) * QKVN + hcol + ch * 8);
    }
    PREFETCH_KV(0, 0); CP_COMMIT();
    PREFETCH_KV(1, 1); CP_COMMIT();

    float accO[8][4];
    #pragma unroll
    for (int nt = 0; nt < 8; nt++)
        #pragma unroll
        for (int r = 0; r < 4; r++) accO[nt][r] = 0.f;
    float mrow[2] = { -1e30f, -1e30f };
    float lrow[2] = { 0.f, 0.f };

    int buf = 0;
    for (int kt = 0; kt < 8; kt++) {
        if (kt < 7) CP_WAIT1(); else CP_WAIT0();
        __syncthreads();
        if (kt + 2 < 8) {
            int nb = buf + 2; if (nb >= 3) nb -= 3;
            PREFETCH_KV(kt + 2, nb); CP_COMMIT();
        }
        const uint32_t kvb = sb + KV0 + buf * KVSTG;

        #pragma unroll
        for (int half = 0; half < 2; half++) {
            // ---- S = Q_hi (K_hi + K_lo)^T over 64 keys ----
            float sacc[8][4];
            #pragma unroll
            for (int nt = 0; nt < 8; nt++)
                #pragma unroll
                for (int r = 0; r < 4; r++) sacc[nt][r] = 0.f;

            #pragma unroll
            for (int ks = 0; ks < 4; ks++) {
                uint32_t aqh[4];
                {
                    const int r = qr + (lane & 15);
                    const uint32_t off = SWZ((uint32_t)(r * 128 + ks * 32 + ((lane >> 4) << 4)));
                    ldsm4(aqh[0], aqh[1], aqh[2], aqh[3], sb + SQH + off);
                }
                #pragma unroll
                for (int np = 0; np < 4; np++) {
                    const int r = half * 64 + np * 16 + (lane & 7) + ((lane >> 4) << 3);
                    const uint32_t off = SWZ((uint32_t)(r * 128 + ks * 32 + (((lane >> 3) & 1) << 4)));
                    uint32_t kh0, kh1, kh2, kh3, kl0, kl1, kl2, kl3;
                    ldsm4(kh0, kh1, kh2, kh3, kvb + AKH + off);
                    ldsm4(kl0, kl1, kl2, kl3, kvb + AKL + off);
                    uint32_t bH0[2] = { kh0, kh1 }, bH1[2] = { kh2, kh3 };
                    uint32_t bL0[2] = { kl0, kl1 }, bL1[2] = { kl2, kl3 };
                    mma_f16(sacc[np * 2],     aqh, bH0);
                    mma_f16(sacc[np * 2],     aqh, bL0);
                    mma_f16(sacc[np * 2 + 1], aqh, bH1);
                    mma_f16(sacc[np * 2 + 1], aqh, bL1);
                }
            }
            #pragma unroll
            for (int nt = 0; nt < 8; nt++)
                #pragma unroll
                for (int r = 0; r < 4; r++) sacc[nt][r] *= 0.125f;

            // ---- online softmax ----
            float mx0 = -1e30f, mx1 = -1e30f;
            #pragma unroll
            for (int nt = 0; nt < 8; nt++) {
                mx0 = fmaxf(mx0, fmaxf(sacc[nt][0], sacc[nt][1]));
                mx1 = fmaxf(mx1, fmaxf(sacc[nt][2], sacc[nt][3]));
            }
            mx0 = fmaxf(mx0, __shfl_xor_sync(0xffffffffu, mx0, 1));
            mx0 = fmaxf(mx0, __shfl_xor_sync(0xffffffffu, mx0, 2));
            mx1 = fmaxf(mx1, __shfl_xor_sync(0xffffffffu, mx1, 1));
            mx1 = fmaxf(mx1, __shfl_xor_sync(0xffffffffu, mx1, 2));
            const float nm0 = fmaxf(mrow[0], mx0), nm1 = fmaxf(mrow[1], mx1);
            const float al0 = __expf(mrow[0] - nm0), al1 = __expf(mrow[1] - nm1);
            mrow[0] = nm0; mrow[1] = nm1;
            float sum0 = 0.f, sum1 = 0.f;
            #pragma unroll
            for (int nt = 0; nt < 8; nt++) {
                sacc[nt][0] = __expf(sacc[nt][0] - nm0);
                sacc[nt][1] = __expf(sacc[nt][1] - nm0);
                sacc[nt][2] = __expf(sacc[nt][2] - nm1);
                sacc[nt][3] = __expf(sacc[nt][3] - nm1);
                sum0 += sacc[nt][0] + sacc[nt][1];
                sum1 += sacc[nt][2] + sacc[nt][3];
                accO[nt][0] *= al0; accO[nt][1] *= al0;
                accO[nt][2] *= al1; accO[nt][3] *= al1;
            }
            sum0 += __shfl_xor_sync(0xffffffffu, sum0, 1);
            sum0 += __shfl_xor_sync(0xffffffffu, sum0, 2);
            sum1 += __shfl_xor_sync(0xffffffffu, sum1, 1);
            sum1 += __shfl_xor_sync(0xffffffffu, sum1, 2);
            lrow[0] = lrow[0] * al0 + sum0;
            lrow[1] = lrow[1] * al1 + sum1;

            // ---- O += P_hi (V_hi + V_lo) ----
            #pragma unroll
            for (int t = 0; t < 4; t++) {
                uint32_t pah[4];
                pah[0] = pack_h2(sacc[2 * t][0],     sacc[2 * t][1]);
                pah[1] = pack_h2(sacc[2 * t][2],     sacc[2 * t][3]);
                pah[2] = pack_h2(sacc[2 * t + 1][0], sacc[2 * t + 1][1]);
                pah[3] = pack_h2(sacc[2 * t + 1][2], sacc[2 * t + 1][3]);
                const int k0 = half * 64 + t * 16;
                #pragma unroll
                for (int np = 0; np < 4; np++) {
                    const int krow = k0 + (lane & 15);
                    const int col = np * 16 + ((lane >> 4) << 3);
                    const uint32_t off = SWZ((uint32_t)(krow * 128 + col * 2));
                    uint32_t vh0, vh1, vh2, vh3, vl0, vl1, vl2, vl3;
                    ldsm4t(vh0, vh1, vh2, vh3, kvb + AVH + off);
                    ldsm4t(vl0, vl1, vl2, vl3, kvb + AVL + off);
                    uint32_t bH0[2] = { vh0, vh1 }, bH1[2] = { vh2, vh3 };
                    uint32_t bL0[2] = { vl0, vl1 }, bL1[2] = { vl2, vl3 };
                    mma_f16(accO[np * 2],     pah, bH0);
                    mma_f16(accO[np * 2],     pah, bL0);
                    mma_f16(accO[np * 2 + 1], pah, bH1);
                    mma_f16(accO[np * 2 + 1], pah, bL1);
                }
            }
        }
        buf++; if (buf >= 3) buf = 0;
    }

    // ---- epilogue: O / l -> fp16 hi gmem (stride Dd) ----
    const float inv0 = 1.f / lrow[0], inv1 = 1.f / lrow[1];
    #pragma unroll
    for (int nt = 0; nt < 8; nt++) {
        const int col = hcol + nt * 8 + 2 * (lane & 3);
        #pragma unroll
        for (int g = 0; g < 2; g++) {
            const size_t tok = qtok + qr + (lane >> 2) + g * 8;
            const float inv = g ? inv1 : inv0;
            ((uint32_t*)Oh)[(tok * Dd + col) >> 1] =
                pack_h2(accO[nt][2 * g] * inv, accO[nt][2 * g + 1] * inv);
        }
    }
}

// ---------------- launch --------------------------------------------------------
extern "C" void kernel_launch(void* const* d_in, const int* in_sizes, int n_in,
                              void* d_out, int out_size)
{
    const float* x   = (const float*)d_in[0];
    const float* wq  = (const float*)d_in[2];
    const float* bq  = (const float*)d_in[3];
    const float* wk  = (const float*)d_in[4];
    const float* bk  = (const float*)d_in[5];
    const float* wv  = (const float*)d_in[6];
    const float* bv  = (const float*)d_in[7];
    const float* wo  = (const float*)d_in[8];
    const float* bo  = (const float*)d_in[9];
    const float* w1  = (const float*)d_in[10];
    const float* b1  = (const float*)d_in[11];
    const float* w2  = (const float*)d_in[12];
    const float* b2  = (const float*)d_in[13];
    const float* g1  = (const float*)d_in[14];
    const float* be1 = (const float*)d_in[15];
    const float* g2  = (const float*)d_in[16];
    const float* be2 = (const float*)d_in[17];
    float* out = (float*)d_out;

    float *x1, *bqkv;
    __half *xnh, *qkvh, *qkvl, *ath, *f1h;
    __half *wqkvh, *wqkvl, *woh, *wol, *w1h, *w1l, *w2h, *w2l;
    cudaGetSymbolAddress((void**)&x1,    g_x1);
    cudaGetSymbolAddress((void**)&bqkv,  g_bqkv);
    cudaGetSymbolAddress((void**)&xnh,   g_xn_hi);
    cudaGetSymbolAddress((void**)&qkvh,  g_qkv_hi);  cudaGetSymbolAddress((void**)&qkvl, g_qkv_lo);
    cudaGetSymbolAddress((void**)&ath,   g_at_hi);
    cudaGetSymbolAddress((void**)&f1h,   g_f1_hi);
    cudaGetSymbolAddress((void**)&wqkvh, g_wqkv_hi); cudaGetSymbolAddress((void**)&wqkvl, g_wqkv_lo);
    cudaGetSymbolAddress((void**)&woh,   g_wo_hi);   cudaGetSymbolAddress((void**)&wol,  g_wo_lo);
    cudaGetSymbolAddress((void**)&w1h,   g_w1_hi);   cudaGetSymbolAddress((void**)&w1l,  g_w1_lo);
    cudaGetSymbolAddress((void**)&w2h,   g_w2_hi);   cudaGetSymbolAddress((void**)&w2l,  g_w2_lo);

    cudaFuncSetAttribute(gemm_mma<1>, cudaFuncAttributeMaxDynamicSharedMemorySize, GEMM_SMEM_DYN);
    cudaFuncSetAttribute(gemm_mma<2>, cudaFuncAttributeMaxDynamicSharedMemorySize, GEMM_SMEM_DYN);
    cudaFuncSetAttribute(gemm_mma<3>, cudaFuncAttributeMaxDynamicSharedMemorySize, GEMM_SMEM_DYN);
    cudaFuncSetAttribute(attn_kernel, cudaFuncAttributeMaxDynamicSharedMemorySize, ATT_SMEM_DYN);

    // weight conversions (wq/wk/wv packed into one [3072 x 1024] buffer)
    const int nDD = Dd * Dd, nW1 = DFFf * Dd;
    conv_hilo<<<nDD / 4096, 256>>>(wq, wqkvh,                 wqkvl,                 nDD / 4);
    conv_hilo<<<nDD / 4096, 256>>>(wk, wqkvh + (size_t)nDD,   wqkvl + (size_t)nDD,   nDD / 4);
    conv_hilo<<<nDD / 4096, 256>>>(wv, wqkvh + (size_t)2*nDD, wqkvl + (size_t)2*nDD, nDD / 4);
    conv_hilo<<<nDD / 4096, 256>>>(wo, woh, wol, nDD / 4);
    conv_hilo<<<nW1 / 4096, 256>>>(w1, w1h, w1l, nW1 / 4);
    conv_hilo<<<nW1 / 4096, 256>>>(w2, w2h, w2l, nW1 / 4);
    pack_bias<<<Dd / 256, 256>>>(bq, bk, bv, bqkv);

    // LN1 -> fp16 hi
    ln_kernel<<<MR, 256>>>(x, xnh, g1, be1);

    // fused QKV projection -> packed fp16 hi/lo [MR x 3072]
    gemm_mma<3><<<dim3(QKVN/128, MR/128), 512, GEMM_SMEM_DYN>>>(
        xnh, wqkvh, wqkvl, bqkv, nullptr, nullptr, qkvh, qkvl, Dd, QKVN);

    // fused flash attention -> fp16 hi
    attn_kernel<<<dim3(Ss/128, Bb*Hh), 256, ATT_SMEM_DYN>>>(qkvh, qkvl, ath);

    // output projection + residual (fp32)
    gemm_mma<1><<<dim3(Dd/128, MR/128), 512, GEMM_SMEM_DYN>>>(
        ath, woh, wol, bo, x, x1, nullptr, nullptr, Dd, Dd);

    // LN2 -> fp16 hi
    ln_kernel<<<MR, 256>>>(x1, xnh, g2, be2);

    // FFN
    gemm_mma<2><<<dim3(DFFf/128, MR/128), 512, GEMM_SMEM_DYN>>>(
        xnh, w1h, w1l, b1, nullptr, nullptr, f1h, nullptr, Dd, DFFf);
    gemm_mma<1><<<dim3(Dd/128, MR/128), 512, GEMM_SMEM_DYN>>>(
        f1h, w2h, w2l, b2, x1, out, nullptr, nullptr, DFFf, Dd);
}

// round 9
// speedup vs baseline: 7.2908x; 1.5582x over previous
#include <cuda_runtime.h>
#include <cuda_fp16.h>
#include <cstdint>

// Problem dims
#define Bb   8
#define Ss   1024
#define Dd   1024
#define Hh   16
#define DKk  64
#define DFFf 4096
#define MR   (Bb * Ss)   // 8192 rows
#define QKVN 3072

// ---------------- scratch (device globals; no allocations allowed) -------------
__device__ float g_x1  [(size_t)MR * Dd];

__device__ __half g_xn_hi [(size_t)MR * Dd];
__device__ __half g_qkv_hi[(size_t)MR * QKVN];
__device__ __half g_at_hi [(size_t)MR * Dd];
__device__ __half g_f1_hi [(size_t)MR * DFFf];
__device__ __half g_wqkv_hi[(size_t)QKVN * Dd];
__device__ __half g_wo_hi[(size_t)Dd * Dd];
__device__ __half g_w1_hi[(size_t)DFFf * Dd];
__device__ __half g_w2_hi[(size_t)Dd * DFFf];
__device__ float g_bqkv[QKVN];

// ---------------- helpers -------------------------------------------------------
__device__ __forceinline__ uint32_t smem_to_u32(const void* p) {
    uint32_t a;
    asm("{ .reg .u64 t; cvta.to.shared.u64 t, %1; cvt.u32.u64 %0, t; }" : "=r"(a) : "l"(p));
    return a;
}
#define SWZ(off) ((off) ^ (((off) >> 3) & 0x70))

#define CP_ASYNC16(dst, src) \
    asm volatile("cp.async.cg.shared.global [%0], [%1], 16;" :: "r"(dst), "l"(src))
#define CP_COMMIT()  asm volatile("cp.async.commit_group;" ::: "memory")
#define CP_WAIT0()   asm volatile("cp.async.wait_group 0;" ::: "memory")
#define CP_WAIT1()   asm volatile("cp.async.wait_group 1;" ::: "memory")

__device__ __forceinline__ void ldsm4(uint32_t& r0, uint32_t& r1, uint32_t& r2, uint32_t& r3,
                                      uint32_t addr) {
    asm volatile("ldmatrix.sync.aligned.m8n8.x4.shared.b16 {%0,%1,%2,%3}, [%4];"
        : "=r"(r0), "=r"(r1), "=r"(r2), "=r"(r3) : "r"(addr));
}
__device__ __forceinline__ void ldsm4t(uint32_t& r0, uint32_t& r1, uint32_t& r2, uint32_t& r3,
                                       uint32_t addr) {
    asm volatile("ldmatrix.sync.aligned.m8n8.x4.trans.shared.b16 {%0,%1,%2,%3}, [%4];"
        : "=r"(r0), "=r"(r1), "=r"(r2), "=r"(r3) : "r"(addr));
}
__device__ __forceinline__ void mma_f16(float* c, const uint32_t* a, const uint32_t* b) {
    asm volatile(
        "mma.sync.aligned.m16n8k16.row.col.f32.f16.f16.f32 "
        "{%0,%1,%2,%3}, {%4,%5,%6,%7}, {%8,%9}, {%0,%1,%2,%3};"
        : "+f"(c[0]), "+f"(c[1]), "+f"(c[2]), "+f"(c[3])
        : "r"(a[0]), "r"(a[1]), "r"(a[2]), "r"(a[3]), "r"(b[0]), "r"(b[1]));
}

__device__ __forceinline__ uint32_t pack_h2(float a, float b) {
    __half ha = __float2half_rn(a), hb = __float2half_rn(b);
    return (uint32_t)__half_as_ushort(ha) | ((uint32_t)__half_as_ushort(hb) << 16);
}

// ---------------- LayerNorm -> fp16 output -------------------------------------
__global__ void __launch_bounds__(256) ln_kernel(
    const float* __restrict__ x, __half* __restrict__ ohi,
    const float* __restrict__ gamma, const float* __restrict__ beta)
{
    const int row = blockIdx.x;
    const float* xr = x + (size_t)row * Dd;
    float s = 0.f, sq = 0.f;
    for (int i = threadIdx.x; i < Dd; i += 256) {
        float v = xr[i]; s += v; sq += v * v;
    }
    #pragma unroll
    for (int o = 16; o > 0; o >>= 1) {
        s  += __shfl_xor_sync(0xffffffffu, s, o);
        sq += __shfl_xor_sync(0xffffffffu, sq, o);
    }
    __shared__ float rs[8], rq[8];
    __shared__ float bmu, brstd;
    const int w = threadIdx.x >> 5, l = threadIdx.x & 31;
    if (l == 0) { rs[w] = s; rq[w] = sq; }
    __syncthreads();
    if (threadIdx.x == 0) {
        float ts = 0.f, tq = 0.f;
        #pragma unroll
        for (int i = 0; i < 8; i++) { ts += rs[i]; tq += rq[i]; }
        float mu  = ts / (float)Dd;
        float var = (tq - (float)Dd * mu * mu) / (float)(Dd - 1);
        bmu = mu; brstd = rsqrtf(var + 1e-5f);
    }
    __syncthreads();
    const float g = gamma[0], be = beta[0];
    const float mu = bmu, rstd = brstd;
    for (int i = threadIdx.x; i < Dd; i += 256)
        ohi[(size_t)row * Dd + i] = __float2half_rn(g * (xr[i] - mu) * rstd + be);
}

// ---------------- fp32 -> fp16 conversion (weights) ----------------------------
__global__ void __launch_bounds__(256) conv_h(
    const float* __restrict__ x, __half* __restrict__ hi, int n4)
{
    const int base = (blockIdx.x * 256 + threadIdx.x) * 4;
    #pragma unroll
    for (int u = 0; u < 4; u++) {
        const int i = base + u;
        if (i >= n4) return;
        float4 v = ((const float4*)x)[i];
        ((uint2*)hi)[i] = make_uint2(pack_h2(v.x, v.y), pack_h2(v.z, v.w));
    }
}

// ---------------- pack Q/K/V biases into one vector ----------------------------
__global__ void pack_bias(const float* __restrict__ b0, const float* __restrict__ b1,
                          const float* __restrict__ b2, float* __restrict__ dst)
{
    const int i = blockIdx.x * 256 + threadIdx.x;
    if (i < Dd) { dst[i] = b0[i]; dst[Dd + i] = b1[i]; dst[2 * Dd + i] = b2[i]; }
}

// ---------------- fp16 mma GEMM: C = A * W^T -----------------------------------
// MODE 1: out fp32 = acc + bias + res
// MODE 2: relu(acc + bias) -> fp16
// MODE 3: (acc + bias)     -> fp16
#define T_AHI 0
#define T_WHI 16384
#define STAGE 32768
#define GEMM_SMEM_DYN 98304   // 3 stages

template<int MODE>
__global__ void __launch_bounds__(512) gemm_mma(
    const __half* __restrict__ Ah, const __half* __restrict__ Wh,
    const float* __restrict__ bias, const float* __restrict__ res,
    float* __restrict__ outF, __half* __restrict__ outHi,
    int K, int N)
{
    extern __shared__ char smem[];
    const uint32_t sbase = smem_to_u32(smem);
    const int tid = threadIdx.x, wid = tid >> 5, lane = tid & 31;
    const int rowBase = blockIdx.y * 128, colBase = blockIdx.x * 128;
    const int warpM = wid & 3, warpN = wid >> 2;     // 4x4 warp grid

    float acc[2][4][4];
    #pragma unroll
    for (int mt = 0; mt < 2; mt++)
        #pragma unroll
        for (int nt = 0; nt < 4; nt++)
            #pragma unroll
            for (int r = 0; r < 4; r++) acc[mt][nt][r] = 0.f;

    const int nch = K >> 6;

    #define PREFETCH(cc, buf) do { \
        const int k0_ = (cc) << 6; \
        const uint32_t sb_ = sbase + (buf) * STAGE; \
        _Pragma("unroll") \
        for (int i_ = 0; i_ < 2; i_++) { \
            const int s_ = tid + 512 * i_; \
            const int row_ = s_ >> 3, c_ = s_ & 7; \
            const uint32_t sw_ = SWZ((uint32_t)(row_ * 128 + c_ * 16)); \
            CP_ASYNC16(sb_ + T_AHI + sw_, Ah + (size_t)(rowBase + row_) * K + k0_ + c_ * 8); \
            CP_ASYNC16(sb_ + T_WHI + sw_, Wh + (size_t)(colBase + row_) * K + k0_ + c_ * 8); \
        } \
    } while (0)

    PREFETCH(0, 0); CP_COMMIT();
    PREFETCH(1, 1); CP_COMMIT();

    int buf = 0;
    for (int c = 0; c < nch; c++) {
        if (c < nch - 1) CP_WAIT1(); else CP_WAIT0();
        __syncthreads();
        if (c + 2 < nch) {
            int nb = buf + 2; if (nb >= 3) nb -= 3;
            PREFETCH(c + 2, nb); CP_COMMIT();
        }
        const uint32_t sb = sbase + buf * STAGE;

        #pragma unroll
        for (int ks = 0; ks < 4; ks++) {
            uint32_t ah[2][4];
            #pragma unroll
            for (int mt = 0; mt < 2; mt++) {
                const int r = warpM * 32 + mt * 16 + (lane & 15);
                const uint32_t off = SWZ((uint32_t)(r * 128 + ks * 32 + ((lane >> 4) << 4)));
                ldsm4(ah[mt][0], ah[mt][1], ah[mt][2], ah[mt][3], sb + T_AHI + off);
            }
            uint32_t bh[4][2];
            #pragma unroll
            for (int ng = 0; ng < 2; ng++) {
                const int r = warpN * 32 + ng * 16 + (lane & 7) + ((lane >> 4) << 3);
                const uint32_t off = SWZ((uint32_t)(r * 128 + ks * 32 + (((lane >> 3) & 1) << 4)));
                uint32_t q0, q1, q2, q3;
                ldsm4(q0, q1, q2, q3, sb + T_WHI + off);
                bh[ng * 2][0] = q0; bh[ng * 2][1] = q1;
                bh[ng * 2 + 1][0] = q2; bh[ng * 2 + 1][1] = q3;
            }
            #pragma unroll
            for (int mt = 0; mt < 2; mt++)
                #pragma unroll
                for (int nt = 0; nt < 4; nt++)
                    mma_f16(acc[mt][nt], ah[mt], bh[nt]);
        }
        buf++; if (buf >= 3) buf = 0;
    }

    // epilogue
    #pragma unroll
    for (int mt = 0; mt < 2; mt++) {
        #pragma unroll
        for (int nt = 0; nt < 4; nt++) {
            const int col = colBase + warpN * 32 + nt * 8 + 2 * (lane & 3);
            const int row0 = rowBase + warpM * 32 + mt * 16 + (lane >> 2);
            const float bx = bias[col], by = bias[col + 1];
            #pragma unroll
            for (int h = 0; h < 2; h++) {
                const int row = row0 + h * 8;
                float v0 = acc[mt][nt][h * 2]     + bx;
                float v1 = acc[mt][nt][h * 2 + 1] + by;
                if (MODE == 2) {
                    v0 = fmaxf(v0, 0.f); v1 = fmaxf(v1, 0.f);
                    ((uint32_t*)outHi)[((size_t)row * N + col) >> 1] = pack_h2(v0, v1);
                } else if (MODE == 3) {
                    ((uint32_t*)outHi)[((size_t)row * N + col) >> 1] = pack_h2(v0, v1);
                } else {
                    const float2 rv = *(const float2*)&res[(size_t)row * N + col];
                    float2 o = { v0 + rv.x, v1 + rv.y };
                    *(float2*)&outF[(size_t)row * N + col] = o;
                }
            }
        }
    }
}

// ---------------- Fused flash attention (fp16 mma) -----------------------------
// Q 16KB + 3 KV stages x 32KB {KH,VH} = 112 KB
#define SQH 0
#define KV0 16384
#define KVSTG 32768
#define AKH 0
#define AVH 16384
#define ATT_SMEM_DYN 114688

__global__ void __launch_bounds__(256) attn_kernel(
    const __half* __restrict__ QKVh, __half* __restrict__ Oh)
{
    extern __shared__ char smem[];
    const uint32_t sb = smem_to_u32(smem);
    const int tid = threadIdx.x, wid = tid >> 5, lane = tid & 31;
    const int bh = blockIdx.y, b = bh >> 4, h = bh & 15;
    const int q0 = blockIdx.x * 128;
    const size_t qtok = (size_t)b * Ss + q0;
    const int hcol = h * DKk;
    const int qr = wid * 16;

    #define PREFETCH_KV(kt_, buf_) do { \
        const uint32_t kvb_ = sb + KV0 + (buf_) * KVSTG; \
        _Pragma("unroll") \
        for (int i_ = 0; i_ < 4; i_++) { \
            const int s_ = tid + 256 * i_; \
            const int row_ = s_ >> 3, ch_ = s_ & 7; \
            const uint32_t sw_ = SWZ((uint32_t)(row_ * 128 + ch_ * 16)); \
            const size_t gk_ = ((size_t)b * Ss + (kt_) * 128 + row_) * QKVN + Dd + hcol + ch_ * 8; \
            CP_ASYNC16(kvb_ + AKH + sw_, QKVh + gk_); \
            CP_ASYNC16(kvb_ + AVH + sw_, QKVh + gk_ + Dd); \
        } \
    } while (0)

    #pragma unroll
    for (int i = 0; i < 4; i++) {
        const int s = tid + 256 * i;
        const int row = s >> 3, ch = s & 7;
        const uint32_t sw = SWZ((uint32_t)(row * 128 + ch * 16));
        CP_ASYNC16(sb + SQH + sw, QKVh + (qtok + row) * QKVN + hcol + ch * 8);
    }
    PREFETCH_KV(0, 0); CP_COMMIT();
    PREFETCH_KV(1, 1); CP_COMMIT();

    float accO[8][4];
    #pragma unroll
    for (int nt = 0; nt < 8; nt++)
        #pragma unroll
        for (int r = 0; r < 4; r++) accO[nt][r] = 0.f;
    float mrow[2] = { -1e30f, -1e30f };
    float lrow[2] = { 0.f, 0.f };

    int buf = 0;
    for (int kt = 0; kt < 8; kt++) {
        if (kt < 7) CP_WAIT1(); else CP_WAIT0();
        __syncthreads();
        if (kt + 2 < 8) {
            int nb = buf + 2; if (nb >= 3) nb -= 3;
            PREFETCH_KV(kt + 2, nb); CP_COMMIT();
        }
        const uint32_t kvb = sb + KV0 + buf * KVSTG;

        #pragma unroll
        for (int half = 0; half < 2; half++) {
            // ---- S = Q K^T over 64 keys ----
            float sacc[8][4];
            #pragma unroll
            for (int nt = 0; nt < 8; nt++)
                #pragma unroll
                for (int r = 0; r < 4; r++) sacc[nt][r] = 0.f;

            #pragma unroll
            for (int ks = 0; ks < 4; ks++) {
                uint32_t aqh[4];
                {
                    const int r = qr + (lane & 15);
                    const uint32_t off = SWZ((uint32_t)(r * 128 + ks * 32 + ((lane >> 4) << 4)));
                    ldsm4(aqh[0], aqh[1], aqh[2], aqh[3], sb + SQH + off);
                }
                #pragma unroll
                for (int np = 0; np < 4; np++) {
                    const int r = half * 64 + np * 16 + (lane & 7) + ((lane >> 4) << 3);
                    const uint32_t off = SWZ((uint32_t)(r * 128 + ks * 32 + (((lane >> 3) & 1) << 4)));
                    uint32_t kh0, kh1, kh2, kh3;
                    ldsm4(kh0, kh1, kh2, kh3, kvb + AKH + off);
                    uint32_t bH0[2] = { kh0, kh1 }, bH1[2] = { kh2, kh3 };
                    mma_f16(sacc[np * 2],     aqh, bH0);
                    mma_f16(sacc[np * 2 + 1], aqh, bH1);
                }
            }
            #pragma unroll
            for (int nt = 0; nt < 8; nt++)
                #pragma unroll
                for (int r = 0; r < 4; r++) sacc[nt][r] *= 0.125f;

            // ---- online softmax ----
            float mx0 = -1e30f, mx1 = -1e30f;
            #pragma unroll
            for (int nt = 0; nt < 8; nt++) {
                mx0 = fmaxf(mx0, fmaxf(sacc[nt][0], sacc[nt][1]));
                mx1 = fmaxf(mx1, fmaxf(sacc[nt][2], sacc[nt][3]));
            }
            mx0 = fmaxf(mx0, __shfl_xor_sync(0xffffffffu, mx0, 1));
            mx0 = fmaxf(mx0, __shfl_xor_sync(0xffffffffu, mx0, 2));
            mx1 = fmaxf(mx1, __shfl_xor_sync(0xffffffffu, mx1, 1));
            mx1 = fmaxf(mx1, __shfl_xor_sync(0xffffffffu, mx1, 2));
            const float nm0 = fmaxf(mrow[0], mx0), nm1 = fmaxf(mrow[1], mx1);
            const float al0 = __expf(mrow[0] - nm0), al1 = __expf(mrow[1] - nm1);
            mrow[0] = nm0; mrow[1] = nm1;
            float sum0 = 0.f, sum1 = 0.f;
            #pragma unroll
            for (int nt = 0; nt < 8; nt++) {
                sacc[nt][0] = __expf(sacc[nt][0] - nm0);
                sacc[nt][1] = __expf(sacc[nt][1] - nm0);
                sacc[nt][2] = __expf(sacc[nt][2] - nm1);
                sacc[nt][3] = __expf(sacc[nt][3] - nm1);
                sum0 += sacc[nt][0] + sacc[nt][1];
                sum1 += sacc[nt][2] + sacc[nt][3];
                accO[nt][0] *= al0; accO[nt][1] *= al0;
                accO[nt][2] *= al1; accO[nt][3] *= al1;
            }
            sum0 += __shfl_xor_sync(0xffffffffu, sum0, 1);
            sum0 += __shfl_xor_sync(0xffffffffu, sum0, 2);
            sum1 += __shfl_xor_sync(0xffffffffu, sum1, 1);
            sum1 += __shfl_xor_sync(0xffffffffu, sum1, 2);
            lrow[0] = lrow[0] * al0 + sum0;
            lrow[1] = lrow[1] * al1 + sum1;

            // ---- O += P V ----
            #pragma unroll
            for (int t = 0; t < 4; t++) {
                uint32_t pah[4];
                pah[0] = pack_h2(sacc[2 * t][0],     sacc[2 * t][1]);
                pah[1] = pack_h2(sacc[2 * t][2],     sacc[2 * t][3]);
                pah[2] = pack_h2(sacc[2 * t + 1][0], sacc[2 * t + 1][1]);
                pah[3] = pack_h2(sacc[2 * t + 1][2], sacc[2 * t + 1][3]);
                const int k0 = half * 64 + t * 16;
                #pragma unroll
                for (int np = 0; np < 4; np++) {
                    const int krow = k0 + (lane & 15);
                    const int col = np * 16 + ((lane >> 4) << 3);
                    const uint32_t off = SWZ((uint32_t)(krow * 128 + col * 2));
                    uint32_t vh0, vh1, vh2, vh3;
                    ldsm4t(vh0, vh1, vh2, vh3, kvb + AVH + off);
                    uint32_t bH0[2] = { vh0, vh1 }, bH1[2] = { vh2, vh3 };
                    mma_f16(accO[np * 2],     pah, bH0);
                    mma_f16(accO[np * 2 + 1], pah, bH1);
                }
            }
        }
        buf++; if (buf >= 3) buf = 0;
    }

    // ---- epilogue: O / l -> fp16 gmem (stride Dd) ----
    const float inv0 = 1.f / lrow[0], inv1 = 1.f / lrow[1];
    #pragma unroll
    for (int nt = 0; nt < 8; nt++) {
        const int col = hcol + nt * 8 + 2 * (lane & 3);
        #pragma unroll
        for (int g = 0; g < 2; g++) {
            const size_t tok = qtok + qr + (lane >> 2) + g * 8;
            const float inv = g ? inv1 : inv0;
            ((uint32_t*)Oh)[(tok * Dd + col) >> 1] =
                pack_h2(accO[nt][2 * g] * inv, accO[nt][2 * g + 1] * inv);
        }
    }
}

// ---------------- launch --------------------------------------------------------
extern "C" void kernel_launch(void* const* d_in, const int* in_sizes, int n_in,
                              void* d_out, int out_size)
{
    const float* x   = (const float*)d_in[0];
    const float* wq  = (const float*)d_in[2];
    const float* bq  = (const float*)d_in[3];
    const float* wk  = (const float*)d_in[4];
    const float* bk  = (const float*)d_in[5];
    const float* wv  = (const float*)d_in[6];
    const float* bv  = (const float*)d_in[7];
    const float* wo  = (const float*)d_in[8];
    const float* bo  = (const float*)d_in[9];
    const float* w1  = (const float*)d_in[10];
    const float* b1  = (const float*)d_in[11];
    const float* w2  = (const float*)d_in[12];
    const float* b2  = (const float*)d_in[13];
    const float* g1  = (const float*)d_in[14];
    const float* be1 = (const float*)d_in[15];
    const float* g2  = (const float*)d_in[16];
    const float* be2 = (const float*)d_in[17];
    float* out = (float*)d_out;

    float *x1, *bqkv;
    __half *xnh, *qkvh, *ath, *f1h, *wqkvh, *woh, *w1h, *w2h;
    cudaGetSymbolAddress((void**)&x1,    g_x1);
    cudaGetSymbolAddress((void**)&bqkv,  g_bqkv);
    cudaGetSymbolAddress((void**)&xnh,   g_xn_hi);
    cudaGetSymbolAddress((void**)&qkvh,  g_qkv_hi);
    cudaGetSymbolAddress((void**)&ath,   g_at_hi);
    cudaGetSymbolAddress((void**)&f1h,   g_f1_hi);
    cudaGetSymbolAddress((void**)&wqkvh, g_wqkv_hi);
    cudaGetSymbolAddress((void**)&woh,   g_wo_hi);
    cudaGetSymbolAddress((void**)&w1h,   g_w1_hi);
    cudaGetSymbolAddress((void**)&w2h,   g_w2_hi);

    cudaFuncSetAttribute(gemm_mma<1>, cudaFuncAttributeMaxDynamicSharedMemorySize, GEMM_SMEM_DYN);
    cudaFuncSetAttribute(gemm_mma<2>, cudaFuncAttributeMaxDynamicSharedMemorySize, GEMM_SMEM_DYN);
    cudaFuncSetAttribute(gemm_mma<3>, cudaFuncAttributeMaxDynamicSharedMemorySize, GEMM_SMEM_DYN);
    cudaFuncSetAttribute(attn_kernel, cudaFuncAttributeMaxDynamicSharedMemorySize, ATT_SMEM_DYN);

    // weight conversions (wq/wk/wv packed into one [3072 x 1024] buffer)
    const int nDD = Dd * Dd, nW1 = DFFf * Dd;
    conv_h<<<nDD / 4096, 256>>>(wq, wqkvh,                 nDD / 4);
    conv_h<<<nDD / 4096, 256>>>(wk, wqkvh + (size_t)nDD,   nDD / 4);
    conv_h<<<nDD / 4096, 256>>>(wv, wqkvh + (size_t)2*nDD, nDD / 4);
    conv_h<<<nDD / 4096, 256>>>(wo, woh, nDD / 4);
    conv_h<<<nW1 / 4096, 256>>>(w1, w1h, nW1 / 4);
    conv_h<<<nW1 / 4096, 256>>>(w2, w2h, nW1 / 4);
    pack_bias<<<Dd / 256, 256>>>(bq, bk, bv, bqkv);

    // LN1 -> fp16
    ln_kernel<<<MR, 256>>>(x, xnh, g1, be1);

    // fused QKV projection -> packed fp16 [MR x 3072]
    gemm_mma<3><<<dim3(QKVN/128, MR/128), 512, GEMM_SMEM_DYN>>>(
        xnh, wqkvh, bqkv, nullptr, nullptr, qkvh, Dd, QKVN);

    // fused flash attention -> fp16
    attn_kernel<<<dim3(Ss/128, Bb*Hh), 256, ATT_SMEM_DYN>>>(qkvh, ath);

    // output projection + residual (fp32)
    gemm_mma<1><<<dim3(Dd/128, MR/128), 512, GEMM_SMEM_DYN>>>(
        ath, woh, bo, x, x1, nullptr, Dd, Dd);

    // LN2 -> fp16
    ln_kernel<<<MR, 256>>>(x1, xnh, g2, be2);

    // FFN
    gemm_mma<2><<<dim3(DFFf/128, MR/128), 512, GEMM_SMEM_DYN>>>(
        xnh, w1h, b1, nullptr, nullptr, f1h, Dd, DFFf);
    gemm_mma<1><<<dim3(Dd/128, MR/128), 512, GEMM_SMEM_DYN>>>(
        f1h, w2h, b2, x1, out, nullptr, DFFf, Dd);
}